// round 2
// baseline (speedup 1.0000x reference)
#include <cuda_runtime.h>
#include <cstdint>

// ---------------------------------------------------------------------------
// Fused GRU cell via mma.sync tf32 (sm_80-compatible PTX: the harness compiles
// through compute_103, so no tcgen05 / TMA 'a'-features are available).
//
// CTA tile: M=128 batch rows x 64 hidden units. B operand = 192 rows:
//   rows [  0, 64): W_gate[n0+u]        -> r gate          (nb 0-7,  wn=0)
//   rows [ 64, 96): Wi/Wh[n0+u], u<32   -> i/h (phase-split, nb 8-11, wn=0)
//   rows [ 96,160): W_gate[512+n0+u]    -> z gate          (nb 0-7,  wn=1)
//   rows [160,192): Wi/Wh[n0+u], u>=32  -> i/h (phase-split, nb 8-11, wn=1)
// K loop: 32 tiles of BK=32 over X=[input|hidden] (K=1024). For kt<16 the ih
// rows hold Wi and accumulate into acc_lo (i_gate); for kt>=16 they hold Wh
// and accumulate into acc_hi (h_gate).
// ---------------------------------------------------------------------------

#define SWZ(x) ((x) ^ (((x) >> 3) & 0x70))

__device__ __forceinline__ uint32_t smem_u32(const void* p) {
    uint32_t a;
    asm("{ .reg .u64 t; cvta.to.shared.u64 t, %1; cvt.u32.u64 %0, t; }"
        : "=r"(a) : "l"(p));
    return a;
}

__device__ __forceinline__ void cp16(uint32_t dst, const void* src) {
    asm volatile("cp.async.cg.shared.global [%0], [%1], 16;"
                 :: "r"(dst), "l"(src) : "memory");
}
#define CP_COMMIT() asm volatile("cp.async.commit_group;" ::: "memory")
#define CP_WAIT(n)  asm volatile("cp.async.wait_group %0;" :: "n"(n) : "memory")

__device__ __forceinline__ void ldsm4(uint32_t& r0, uint32_t& r1,
                                      uint32_t& r2, uint32_t& r3, uint32_t addr) {
    asm volatile("ldmatrix.sync.aligned.m8n8.x4.shared.b16 {%0,%1,%2,%3}, [%4];"
                 : "=r"(r0), "=r"(r1), "=r"(r2), "=r"(r3) : "r"(addr));
}

__device__ __forceinline__ void mma8(float* c, const uint32_t* a,
                                     uint32_t b0, uint32_t b1) {
    asm volatile(
        "mma.sync.aligned.m16n8k8.row.col.f32.tf32.tf32.f32 "
        "{%0,%1,%2,%3}, {%4,%5,%6,%7}, {%8,%9}, {%0,%1,%2,%3};"
        : "+f"(c[0]), "+f"(c[1]), "+f"(c[2]), "+f"(c[3])
        : "r"(a[0]), "r"(a[1]), "r"(a[2]), "r"(a[3]), "r"(b0), "r"(b1));
}

__device__ __forceinline__ float fsigmoid(float x) {
    return 1.0f / (1.0f + __expf(-x));
}
__device__ __forceinline__ float ftanh(float x) {
    float e = __expf(2.0f * x);          // overflow->inf, underflow->0: safe
    return 1.0f - 2.0f / (e + 1.0f);
}

// ---- geometry ----
static constexpr int NSTAGE      = 4;
static constexpr int A_BYTES     = 128 * 128;          // 128 rows x 32 fp32
static constexpr int B_BYTES     = 192 * 128;          // 192 rows x 32 fp32
static constexpr int STAGE_BYTES = A_BYTES + B_BYTES;  // 40960
static constexpr int SMEM_BYTES  = 1024 + NSTAGE * STAGE_BYTES + 128; // +align
static constexpr int GP          = 72;                 // gate-staging pitch

__device__ __forceinline__ void fill_stage(
    int kt, uint32_t stg, int tid, int m0, int n0,
    const float* __restrict__ input, const float* __restrict__ hidden,
    const float* __restrict__ Wg, const float* __restrict__ Wi,
    const float* __restrict__ Wh)
{
    const float* xa  = (kt < 16) ? input : hidden;
    const float* wih = (kt < 16) ? Wi : Wh;
    const int kloc = (kt & 15) * 32;   // col offset within input/hidden/Wi/Wh
    const int kg   = kt * 32;          // col offset within W_gate (K=1024)

    // A tile: 128 rows x 8 chunks(16B) = 1024 units / 256 thr = 4 each
    #pragma unroll
    for (int i = 0; i < 4; i++) {
        int u = tid + i * 256, r = u >> 3, cu = u & 7;
        cp16(stg + SWZ((uint32_t)(r * 128 + cu * 16)),
             xa + (m0 + r) * 512 + kloc + cu * 4);
    }
    // B tile: 192 rows x 8 chunks = 1536 units / 256 thr = 6 each
    const uint32_t bb = stg + A_BYTES;
    #pragma unroll
    for (int i = 0; i < 6; i++) {
        int u = tid + i * 256, r = u >> 3, cu = u & 7;
        const float* src;
        if (r < 64)        src = Wg  + (n0 + r) * 1024 + kg + cu * 4;         // r gate
        else if (r < 96)   src = wih + (n0 + r - 64) * 512 + kloc + cu * 4;   // ih lo
        else if (r < 160)  src = Wg  + (512 + n0 + r - 96) * 1024 + kg + cu * 4; // z
        else               src = wih + (n0 + r - 128) * 512 + kloc + cu * 4;  // ih hi
        cp16(bb + SWZ((uint32_t)(r * 128 + cu * 16)), src);
    }
}

template <bool PH>  // PH=false: kt<16 (i phase), PH=true: kt>=16 (h phase)
__device__ __forceinline__ void compute_tile(
    uint32_t Ab, uint32_t Bb, int wm, int wn, int lane,
    float (&alo)[2][12][4], float (&ahi)[2][4][4])
{
    const uint32_t arow = (uint32_t)(wm * 32 + (lane & 7) + ((lane >> 3) & 1) * 8);
    const uint32_t acb  = (uint32_t)((lane >> 4) * 16);
    const uint32_t brow = (uint32_t)(wn * 96 + ((lane >> 4) * 8) + (lane & 7));
    const uint32_t bcb  = (uint32_t)(((lane >> 3) & 1) * 16);

    #pragma unroll
    for (int ks = 0; ks < 4; ks++) {
        uint32_t a[2][4];
        #pragma unroll
        for (int mi = 0; mi < 2; mi++) {
            uint32_t off = (arow + mi * 16) * 128 + (uint32_t)(ks * 32) + acb;
            ldsm4(a[mi][0], a[mi][1], a[mi][2], a[mi][3], Ab + SWZ(off));
        }
        uint32_t b[12][2];
        #pragma unroll
        for (int p = 0; p < 6; p++) {
            uint32_t off = (brow + p * 16) * 128 + (uint32_t)(ks * 32) + bcb;
            ldsm4(b[2 * p][0], b[2 * p][1], b[2 * p + 1][0], b[2 * p + 1][1],
                  Bb + SWZ(off));
        }
        #pragma unroll
        for (int mi = 0; mi < 2; mi++) {
            #pragma unroll
            for (int nb = 0; nb < 12; nb++) {
                if (PH && nb >= 8)
                    mma8(ahi[mi][nb - 8], a[mi], b[nb][0], b[nb][1]);
                else
                    mma8(alo[mi][nb], a[mi], b[nb][0], b[nb][1]);
            }
        }
    }
}

__global__ void __launch_bounds__(256, 1)
gru_mma_kernel(const float* __restrict__ input, const float* __restrict__ hidden,
               const float* __restrict__ Wg, const float* __restrict__ bg,
               const float* __restrict__ Wi, const float* __restrict__ bi,
               const float* __restrict__ Wh, const float* __restrict__ bh,
               float* __restrict__ out)
{
    extern __shared__ char dsm[];
    const int tid  = threadIdx.x;
    const int wid  = tid >> 5;
    const int lane = tid & 31;
    const int wm   = wid >> 1;          // 0..3 (M)
    const int wn   = wid & 1;           // 0..1 (N')
    const int n0 = blockIdx.x * 64;     // hidden-unit slice
    const int m0 = blockIdx.y * 128;    // batch-row slice

    const uint32_t raw = smem_u32(dsm);
    const uint32_t sb  = (raw + 127u) & ~127u;
    char* gb = dsm + (sb - raw);

    // biases: br[64]@0, bz@64, bi@128, bh@192 (floats)
    float* sbias = (float*)gb;
    {
        int g = tid >> 6, j = tid & 63;
        float v;
        if (g == 0)      v = bg[n0 + j];
        else if (g == 1) v = bg[512 + n0 + j];
        else if (g == 2) v = bi[n0 + j];
        else             v = bh[n0 + j];
        sbias[tid] = v;
    }

    float alo[2][12][4];
    float ahi[2][4][4];
    #pragma unroll
    for (int mi = 0; mi < 2; mi++) {
        #pragma unroll
        for (int nb = 0; nb < 12; nb++)
            #pragma unroll
            for (int e = 0; e < 4; e++) alo[mi][nb][e] = 0.0f;
        #pragma unroll
        for (int nb = 0; nb < 4; nb++)
            #pragma unroll
            for (int e = 0; e < 4; e++) ahi[mi][nb][e] = 0.0f;
    }

    // prefetch stages 0..2
    #pragma unroll
    for (int p = 0; p < 3; p++) {
        fill_stage(p, sb + 1024 + (uint32_t)p * STAGE_BYTES, tid, m0, n0,
                   input, hidden, Wg, Wi, Wh);
        CP_COMMIT();
    }

    #pragma unroll 1
    for (int kt = 0; kt < 32; kt++) {
        const uint32_t stg = sb + 1024 + (uint32_t)(kt & 3) * STAGE_BYTES;
        CP_WAIT(2);
        __syncthreads();
        if (kt < 16) compute_tile<false>(stg, stg + A_BYTES, wm, wn, lane, alo, ahi);
        else         compute_tile<true >(stg, stg + A_BYTES, wm, wn, lane, alo, ahi);
        __syncthreads();
        if (kt + 3 < 32) {
            fill_stage(kt + 3, sb + 1024 + (uint32_t)((kt + 3) & 3) * STAGE_BYTES,
                       tid, m0, n0, input, hidden, Wg, Wi, Wh);
        }
        CP_COMMIT();   // empty group when no fill keeps wait_group accounting uniform
    }
    __syncthreads();

    // ---- epilogue ----
    // c-frag layout (m16n8 f32): e0:(row,col) e1:(row,col+1) e2:(row+8,col) e3:(row+8,col+1)
    // with row = wm*32 + mi*16 + lane/4, col = nb*8 + 2*(lane%4).
    float* s_r = (float*)(gb + 1024);        // [128][GP], reuses stage smem
    float* s_z = s_r + 128 * GP;
    const float* sb_r = sbias;
    const float* sb_z = sbias + 64;
    const float* sb_i = sbias + 128;
    const float* sb_h = sbias + 192;

    // phase 1: r (wn=0) / z (wn=1) gate frags (nb 0..7); value = alo + ahi? no —
    // r/z accumulate in alo across all kt (nb<8 always goes to alo). sigmoid+bias.
    {
        float* sdst      = (wn == 0) ? s_r : s_z;
        const float* sbg = (wn == 0) ? sb_r : sb_z;
        #pragma unroll
        for (int mi = 0; mi < 2; mi++) {
            #pragma unroll
            for (int nb = 0; nb < 8; nb++) {
                const int u0 = nb * 8 + 2 * (lane & 3);
                const int mr = wm * 32 + mi * 16 + (lane >> 2);
                const float b0 = sbg[u0], b1 = sbg[u0 + 1];
                sdst[mr * GP + u0]           = fsigmoid(alo[mi][nb][0] + b0);
                sdst[mr * GP + u0 + 1]       = fsigmoid(alo[mi][nb][1] + b1);
                sdst[(mr + 8) * GP + u0]     = fsigmoid(alo[mi][nb][2] + b0);
                sdst[(mr + 8) * GP + u0 + 1] = fsigmoid(alo[mi][nb][3] + b1);
            }
        }
    }
    __syncthreads();

    // phase 2: every warp combines its i (alo nb 8..11) and h (ahi) fragments.
    // units: wn*32 + hb*8 + 2*(lane%4); rows: wm*32 + mi*16 + lane/4 (+8)
    {
        const int uoff = wn * 32;
        #pragma unroll
        for (int mi = 0; mi < 2; mi++) {
            #pragma unroll
            for (int hb = 0; hb < 4; hb++) {
                const int u0 = uoff + hb * 8 + 2 * (lane & 3);
                const int mr = wm * 32 + mi * 16 + (lane >> 2);
                const float bi0 = sb_i[u0], bi1 = sb_i[u0 + 1];
                const float bh0 = sb_h[u0], bh1 = sb_h[u0 + 1];
                #pragma unroll
                for (int half = 0; half < 2; half++) {
                    const int m = mr + 8 * half;
                    const float iv0 = alo[mi][8 + hb][2 * half];
                    const float iv1 = alo[mi][8 + hb][2 * half + 1];
                    const float hv0 = ahi[mi][hb][2 * half];
                    const float hv1 = ahi[mi][hb][2 * half + 1];
                    const float rv0 = s_r[m * GP + u0], rv1 = s_r[m * GP + u0 + 1];
                    const float zv0 = s_z[m * GP + u0], zv1 = s_z[m * GP + u0 + 1];
                    const float2 hg = *(const float2*)&hidden[(m0 + m) * 512 + n0 + u0];
                    const float ng0 = ftanh(iv0 + bi0 + rv0 * (hv0 + bh0));
                    const float ng1 = ftanh(iv1 + bi1 + rv1 * (hv1 + bh1));
                    float2 o;
                    o.x = (1.0f - zv0) * ng0 + zv0 * hg.x;
                    o.y = (1.0f - zv1) * ng1 + zv1 * hg.y;
                    *(float2*)&out[(m0 + m) * 512 + n0 + u0] = o;
                }
            }
        }
    }
}

extern "C" void kernel_launch(void* const* d_in, const int* in_sizes, int n_in,
                              void* d_out, int out_size)
{
    const float* input  = (const float*)d_in[0];
    const float* hidden = (const float*)d_in[1];
    const float* Wg     = (const float*)d_in[2];
    const float* bg     = (const float*)d_in[3];
    const float* Wi     = (const float*)d_in[4];
    const float* bi     = (const float*)d_in[5];
    const float* Wh     = (const float*)d_in[6];
    const float* bh     = (const float*)d_in[7];
    float* out = (float*)d_out;

    cudaFuncSetAttribute(gru_mma_kernel,
                         cudaFuncAttributeMaxDynamicSharedMemorySize, SMEM_BYTES);
    // grid.x = 8 n-slices (fastest -> concurrent CTAs share X tiles in L2),
    // grid.y = 128 batch tiles
    gru_mma_kernel<<<dim3(8, 128), 256, SMEM_BYTES>>>(
        input, hidden, Wg, bg, Wi, bi, Wh, bh, out);
}

// round 3
// speedup vs baseline: 1.0046x; 1.0046x over previous
#include <cuda_runtime.h>
#include <cstdint>

// ---------------------------------------------------------------------------
// Fused GRU cell via mma.sync tf32 (compute_103-safe PTX; no tcgen05/TMA).
// R3: 1 barrier per k-iter (was 2), fill-before-compute, explicit double-
// buffered fragment pipeline inside compute_tile.
//
// CTA tile: M=128 batch rows x 64 hidden units. B operand = 192 rows:
//   rows [  0, 64): W_gate[n0+u]        -> r gate          (nb 0-7,  wn=0)
//   rows [ 64, 96): Wi/Wh[n0+u], u<32   -> i/h (phase-split, nb 8-11, wn=0)
//   rows [ 96,160): W_gate[512+n0+u]    -> z gate          (nb 0-7,  wn=1)
//   rows [160,192): Wi/Wh[n0+u], u>=32  -> i/h (phase-split, nb 8-11, wn=1)
// K loop: 32 tiles of BK=32 over X=[input|hidden] (K=1024). For kt<16 the ih
// rows hold Wi and accumulate into alo (i_gate); for kt>=16 they hold Wh and
// accumulate into ahi (h_gate).
// ---------------------------------------------------------------------------

#define SWZ(x) ((x) ^ (((x) >> 3) & 0x70))

__device__ __forceinline__ uint32_t smem_u32(const void* p) {
    uint32_t a;
    asm("{ .reg .u64 t; cvta.to.shared.u64 t, %1; cvt.u32.u64 %0, t; }"
        : "=r"(a) : "l"(p));
    return a;
}

__device__ __forceinline__ void cp16(uint32_t dst, const void* src) {
    asm volatile("cp.async.cg.shared.global [%0], [%1], 16;"
                 :: "r"(dst), "l"(src) : "memory");
}
#define CP_COMMIT() asm volatile("cp.async.commit_group;" ::: "memory")
#define CP_WAIT(n)  asm volatile("cp.async.wait_group %0;" :: "n"(n) : "memory")

__device__ __forceinline__ void ldsm4(uint32_t& r0, uint32_t& r1,
                                      uint32_t& r2, uint32_t& r3, uint32_t addr) {
    asm volatile("ldmatrix.sync.aligned.m8n8.x4.shared.b16 {%0,%1,%2,%3}, [%4];"
                 : "=r"(r0), "=r"(r1), "=r"(r2), "=r"(r3) : "r"(addr));
}

__device__ __forceinline__ void mma8(float* c, const uint32_t* a,
                                     uint32_t b0, uint32_t b1) {
    asm volatile(
        "mma.sync.aligned.m16n8k8.row.col.f32.tf32.tf32.f32 "
        "{%0,%1,%2,%3}, {%4,%5,%6,%7}, {%8,%9}, {%0,%1,%2,%3};"
        : "+f"(c[0]), "+f"(c[1]), "+f"(c[2]), "+f"(c[3])
        : "r"(a[0]), "r"(a[1]), "r"(a[2]), "r"(a[3]), "r"(b0), "r"(b1));
}

__device__ __forceinline__ float fsigmoid(float x) {
    return 1.0f / (1.0f + __expf(-x));
}
__device__ __forceinline__ float ftanh(float x) {
    float e = __expf(2.0f * x);          // overflow->inf, underflow->0: safe
    return 1.0f - 2.0f / (e + 1.0f);
}

// ---- geometry ----
static constexpr int NSTAGE      = 4;
static constexpr int A_BYTES     = 128 * 128;          // 128 rows x 32 fp32
static constexpr int B_BYTES     = 192 * 128;          // 192 rows x 32 fp32
static constexpr int STAGE_BYTES = A_BYTES + B_BYTES;  // 40960
static constexpr int SMEM_BYTES  = 1024 + NSTAGE * STAGE_BYTES + 128; // +align
static constexpr int GP          = 72;                 // gate-staging pitch

__device__ __forceinline__ void fill_stage(
    int kt, uint32_t stg, int tid, int m0, int n0,
    const float* __restrict__ input, const float* __restrict__ hidden,
    const float* __restrict__ Wg, const float* __restrict__ Wi,
    const float* __restrict__ Wh)
{
    const float* xa  = (kt < 16) ? input : hidden;
    const float* wih = (kt < 16) ? Wi : Wh;
    const int kloc = (kt & 15) * 32;   // col offset within input/hidden/Wi/Wh
    const int kg   = kt * 32;          // col offset within W_gate (K=1024)

    // A tile: 128 rows x 8 chunks(16B) = 1024 units / 256 thr = 4 each
    #pragma unroll
    for (int i = 0; i < 4; i++) {
        int u = tid + i * 256, r = u >> 3, cu = u & 7;
        cp16(stg + SWZ((uint32_t)(r * 128 + cu * 16)),
             xa + (m0 + r) * 512 + kloc + cu * 4);
    }
    // B tile: 192 rows x 8 chunks = 1536 units / 256 thr = 6 each
    const uint32_t bb = stg + A_BYTES;
    #pragma unroll
    for (int i = 0; i < 6; i++) {
        int u = tid + i * 256, r = u >> 3, cu = u & 7;
        const float* src;
        if (r < 64)        src = Wg  + (n0 + r) * 1024 + kg + cu * 4;            // r gate
        else if (r < 96)   src = wih + (n0 + r - 64) * 512 + kloc + cu * 4;      // ih lo
        else if (r < 160)  src = Wg  + (512 + n0 + r - 96) * 1024 + kg + cu * 4; // z
        else               src = wih + (n0 + r - 128) * 512 + kloc + cu * 4;     // ih hi
        cp16(bb + SWZ((uint32_t)(r * 128 + cu * 16)), src);
    }
}

__device__ __forceinline__ void load_frags(
    uint32_t Ab, uint32_t Bb, int ks,
    uint32_t arow, uint32_t acb, uint32_t brow, uint32_t bcb,
    uint32_t (&a)[2][4], uint32_t (&b)[12][2])
{
    #pragma unroll
    for (int mi = 0; mi < 2; mi++) {
        uint32_t off = (arow + mi * 16) * 128 + (uint32_t)(ks * 32) + acb;
        ldsm4(a[mi][0], a[mi][1], a[mi][2], a[mi][3], Ab + SWZ(off));
    }
    #pragma unroll
    for (int p = 0; p < 6; p++) {
        uint32_t off = (brow + p * 16) * 128 + (uint32_t)(ks * 32) + bcb;
        ldsm4(b[2 * p][0], b[2 * p][1], b[2 * p + 1][0], b[2 * p + 1][1],
              Bb + SWZ(off));
    }
}

template <bool PH>  // PH=false: kt<16 (i phase), PH=true: kt>=16 (h phase)
__device__ __forceinline__ void compute_tile(
    uint32_t Ab, uint32_t Bb, int wm, int wn, int lane,
    float (&alo)[2][12][4], float (&ahi)[2][4][4])
{
    const uint32_t arow = (uint32_t)(wm * 32 + (lane & 7) + ((lane >> 3) & 1) * 8);
    const uint32_t acb  = (uint32_t)((lane >> 4) * 16);
    const uint32_t brow = (uint32_t)(wn * 96 + ((lane >> 4) * 8) + (lane & 7));
    const uint32_t bcb  = (uint32_t)(((lane >> 3) & 1) * 16);

    uint32_t a[2][2][4];    // [buf][mi][reg]
    uint32_t b[2][12][2];   // [buf][nb][reg]
    load_frags(Ab, Bb, 0, arow, acb, brow, bcb, a[0], b[0]);

    #pragma unroll
    for (int ks = 0; ks < 4; ks++) {
        const int cur = ks & 1, nxt = cur ^ 1;
        if (ks < 3)   // prefetch ks+1 fragments; latency hidden under MMAs below
            load_frags(Ab, Bb, ks + 1, arow, acb, brow, bcb, a[nxt], b[nxt]);
        #pragma unroll
        for (int mi = 0; mi < 2; mi++) {
            #pragma unroll
            for (int nb = 0; nb < 12; nb++) {
                if (PH && nb >= 8)
                    mma8(ahi[mi][nb - 8], a[cur][mi], b[cur][nb][0], b[cur][nb][1]);
                else
                    mma8(alo[mi][nb], a[cur][mi], b[cur][nb][0], b[cur][nb][1]);
            }
        }
    }
}

__global__ void __launch_bounds__(256, 1)
gru_mma_kernel(const float* __restrict__ input, const float* __restrict__ hidden,
               const float* __restrict__ Wg, const float* __restrict__ bg,
               const float* __restrict__ Wi, const float* __restrict__ bi,
               const float* __restrict__ Wh, const float* __restrict__ bh,
               float* __restrict__ out)
{
    extern __shared__ char dsm[];
    const int tid  = threadIdx.x;
    const int lane = tid & 31;
    const int wid  = tid >> 5;
    const int wm   = wid >> 1;          // 0..3 (M)
    const int wn   = wid & 1;           // 0..1 (N')
    const int n0 = blockIdx.x * 64;     // hidden-unit slice
    const int m0 = blockIdx.y * 128;    // batch-row slice

    const uint32_t raw = smem_u32(dsm);
    const uint32_t sb  = (raw + 127u) & ~127u;
    char* gb = dsm + (sb - raw);

    // biases: br[64]@0, bz@64, bi@128, bh@192 (floats)
    float* sbias = (float*)gb;
    {
        int g = tid >> 6, j = tid & 63;
        float v;
        if (g == 0)      v = bg[n0 + j];
        else if (g == 1) v = bg[512 + n0 + j];
        else if (g == 2) v = bi[n0 + j];
        else             v = bh[n0 + j];
        sbias[tid] = v;
    }

    float alo[2][12][4];
    float ahi[2][4][4];
    #pragma unroll
    for (int mi = 0; mi < 2; mi++) {
        #pragma unroll
        for (int nb = 0; nb < 12; nb++)
            #pragma unroll
            for (int e = 0; e < 4; e++) alo[mi][nb][e] = 0.0f;
        #pragma unroll
        for (int nb = 0; nb < 4; nb++)
            #pragma unroll
            for (int e = 0; e < 4; e++) ahi[mi][nb][e] = 0.0f;
    }

    // prefetch stages 0..2
    #pragma unroll
    for (int p = 0; p < 3; p++) {
        fill_stage(p, sb + 1024 + (uint32_t)p * STAGE_BYTES, tid, m0, n0,
                   input, hidden, Wg, Wi, Wh);
        CP_COMMIT();
    }

    // Single barrier per iteration. The barrier at iter kt guarantees all
    // warps finished compute(kt-1); fill(kt+3) overwrites stage (kt-1)&3,
    // which that barrier protects. fill precedes compute so LDGSTS latency
    // hides under the 96 MMAs.
    #pragma unroll 1
    for (int kt = 0; kt < 32; kt++) {
        const uint32_t stg = sb + 1024 + (uint32_t)(kt & 3) * STAGE_BYTES;
        CP_WAIT(2);
        __syncthreads();
        if (kt + 3 < 32) {
            fill_stage(kt + 3, sb + 1024 + (uint32_t)((kt + 3) & 3) * STAGE_BYTES,
                       tid, m0, n0, input, hidden, Wg, Wi, Wh);
        }
        CP_COMMIT();   // empty group when no fill keeps wait_group accounting uniform
        if (kt < 16) compute_tile<false>(stg, stg + A_BYTES, wm, wn, lane, alo, ahi);
        else         compute_tile<true >(stg, stg + A_BYTES, wm, wn, lane, alo, ahi);
    }

    // ---- epilogue ----
    // c-frag layout (m16n8 f32): e0:(row,col) e1:(row,col+1) e2:(row+8,col)
    // e3:(row+8,col+1); row = wm*32 + mi*16 + lane/4, col = nb*8 + 2*(lane%4).
    // Staging lives in stage-0/1 smem; the slowest warp is in compute(31)
    // reading stage 3, so no barrier is needed before phase 1 writes.
    float* s_r = (float*)(gb + 1024);        // [128][GP]
    float* s_z = s_r + 128 * GP;
    const float* sb_r = sbias;
    const float* sb_z = sbias + 64;
    const float* sb_i = sbias + 128;
    const float* sb_h = sbias + 192;

    // phase 1: r (wn=0) / z (wn=1) gates from alo nb 0..7 -> sigmoid -> smem
    {
        float* sdst      = (wn == 0) ? s_r : s_z;
        const float* sbg = (wn == 0) ? sb_r : sb_z;
        #pragma unroll
        for (int mi = 0; mi < 2; mi++) {
            #pragma unroll
            for (int nb = 0; nb < 8; nb++) {
                const int u0 = nb * 8 + 2 * (lane & 3);
                const int mr = wm * 32 + mi * 16 + (lane >> 2);
                const float b0 = sbg[u0], b1 = sbg[u0 + 1];
                sdst[mr * GP + u0]           = fsigmoid(alo[mi][nb][0] + b0);
                sdst[mr * GP + u0 + 1]       = fsigmoid(alo[mi][nb][1] + b1);
                sdst[(mr + 8) * GP + u0]     = fsigmoid(alo[mi][nb][2] + b0);
                sdst[(mr + 8) * GP + u0 + 1] = fsigmoid(alo[mi][nb][3] + b1);
            }
        }
    }
    __syncthreads();

    // phase 2: combine i (alo nb 8..11) + h (ahi) + staged r/z -> out
    {
        const int uoff = wn * 32;
        #pragma unroll
        for (int mi = 0; mi < 2; mi++) {
            #pragma unroll
            for (int hb = 0; hb < 4; hb++) {
                const int u0 = uoff + hb * 8 + 2 * (lane & 3);
                const int mr = wm * 32 + mi * 16 + (lane >> 2);
                const float bi0 = sb_i[u0], bi1 = sb_i[u0 + 1];
                const float bh0 = sb_h[u0], bh1 = sb_h[u0 + 1];
                #pragma unroll
                for (int half = 0; half < 2; half++) {
                    const int m = mr + 8 * half;
                    const float iv0 = alo[mi][8 + hb][2 * half];
                    const float iv1 = alo[mi][8 + hb][2 * half + 1];
                    const float hv0 = ahi[mi][hb][2 * half];
                    const float hv1 = ahi[mi][hb][2 * half + 1];
                    const float rv0 = s_r[m * GP + u0], rv1 = s_r[m * GP + u0 + 1];
                    const float zv0 = s_z[m * GP + u0], zv1 = s_z[m * GP + u0 + 1];
                    const float2 hg = *(const float2*)&hidden[(m0 + m) * 512 + n0 + u0];
                    const float ng0 = ftanh(iv0 + bi0 + rv0 * (hv0 + bh0));
                    const float ng1 = ftanh(iv1 + bi1 + rv1 * (hv1 + bh1));
                    float2 o;
                    o.x = (1.0f - zv0) * ng0 + zv0 * hg.x;
                    o.y = (1.0f - zv1) * ng1 + zv1 * hg.y;
                    *(float2*)&out[(m0 + m) * 512 + n0 + u0] = o;
                }
            }
        }
    }
}

extern "C" void kernel_launch(void* const* d_in, const int* in_sizes, int n_in,
                              void* d_out, int out_size)
{
    const float* input  = (const float*)d_in[0];
    const float* hidden = (const float*)d_in[1];
    const float* Wg     = (const float*)d_in[2];
    const float* bg     = (const float*)d_in[3];
    const float* Wi     = (const float*)d_in[4];
    const float* bi     = (const float*)d_in[5];
    const float* Wh     = (const float*)d_in[6];
    const float* bh     = (const float*)d_in[7];
    float* out = (float*)d_out;

    cudaFuncSetAttribute(gru_mma_kernel,
                         cudaFuncAttributeMaxDynamicSharedMemorySize, SMEM_BYTES);
    // grid.x = 8 n-slices (fastest -> concurrent CTAs share X tiles in L2),
    // grid.y = 128 batch tiles
    gru_mma_kernel<<<dim3(8, 128), 256, SMEM_BYTES>>>(
        input, hidden, Wg, bg, Wi, bi, Wh, bh, out);
}

// round 4
// speedup vs baseline: 1.0886x; 1.0836x over previous
#include <cuda_runtime.h>
#include <cstdint>

// ---------------------------------------------------------------------------
// Fused GRU cell via mma.sync tf32 (compute_103-safe PTX; no tcgen05/TMA).
// R4: CTA tile M=64 x 192 B-rows, 2 CTAs/SM (occ 2x), warps 2(M)x4(N),
// per-wn interleaved slice [r:16|z:16|ih:16] -> register-resident epilogue.
//
// B operand rows (192), per wn slice s = wn*48:
//   rows [s+ 0, s+16): W_gate[n0+wn*16+u]        -> r gate (nb 0,1)
//   rows [s+16, s+32): W_gate[512+n0+wn*16+u]    -> z gate (nb 2,3)
//   rows [s+32, s+48): Wi/Wh [n0+wn*16+u]        -> i/h    (nb 4,5, phase split)
// K loop: 32 tiles of BK=32 over X=[input|hidden] (K=1024). kt<16: ih rows
// hold Wi, accumulate alo (i). kt>=16: Wh, accumulate ahi (h).
// ---------------------------------------------------------------------------

#define SWZ(x) ((x) ^ (((x) >> 3) & 0x70))

__device__ __forceinline__ uint32_t smem_u32(const void* p) {
    uint32_t a;
    asm("{ .reg .u64 t; cvta.to.shared.u64 t, %1; cvt.u32.u64 %0, t; }"
        : "=r"(a) : "l"(p));
    return a;
}

__device__ __forceinline__ void cp16(uint32_t dst, const void* src) {
    asm volatile("cp.async.cg.shared.global [%0], [%1], 16;"
                 :: "r"(dst), "l"(src) : "memory");
}
#define CP_COMMIT() asm volatile("cp.async.commit_group;" ::: "memory")
#define CP_WAIT(n)  asm volatile("cp.async.wait_group %0;" :: "n"(n) : "memory")

__device__ __forceinline__ void ldsm4(uint32_t& r0, uint32_t& r1,
                                      uint32_t& r2, uint32_t& r3, uint32_t addr) {
    asm volatile("ldmatrix.sync.aligned.m8n8.x4.shared.b16 {%0,%1,%2,%3}, [%4];"
                 : "=r"(r0), "=r"(r1), "=r"(r2), "=r"(r3) : "r"(addr));
}

__device__ __forceinline__ void mma8(float* c, const uint32_t* a,
                                     uint32_t b0, uint32_t b1) {
    asm volatile(
        "mma.sync.aligned.m16n8k8.row.col.f32.tf32.tf32.f32 "
        "{%0,%1,%2,%3}, {%4,%5,%6,%7}, {%8,%9}, {%0,%1,%2,%3};"
        : "+f"(c[0]), "+f"(c[1]), "+f"(c[2]), "+f"(c[3])
        : "r"(a[0]), "r"(a[1]), "r"(a[2]), "r"(a[3]), "r"(b0), "r"(b1));
}

__device__ __forceinline__ float fsigmoid(float x) {
    return 1.0f / (1.0f + __expf(-x));
}
__device__ __forceinline__ float ftanh(float x) {
    float e = __expf(2.0f * x);          // overflow->inf, underflow->0: safe
    return 1.0f - 2.0f / (e + 1.0f);
}

// ---- geometry ----
static constexpr int NSTAGE      = 3;
static constexpr int A_BYTES     = 64 * 128;           // 64 rows x 32 fp32
static constexpr int B_BYTES     = 192 * 128;          // 192 rows x 32 fp32
static constexpr int STAGE_BYTES = A_BYTES + B_BYTES;  // 32768
static constexpr int SMEM_BYTES  = 1024 + NSTAGE * STAGE_BYTES + 128;

__device__ __forceinline__ void fill_stage(
    int kt, uint32_t stg, int tid, int m0, int n0,
    const float* __restrict__ input, const float* __restrict__ hidden,
    const float* __restrict__ Wg, const float* __restrict__ Wi,
    const float* __restrict__ Wh)
{
    const float* xa  = (kt < 16) ? input : hidden;
    const float* wih = (kt < 16) ? Wi : Wh;
    const int kloc = (kt & 15) * 32;   // col offset within input/hidden/Wi/Wh
    const int kg   = kt * 32;          // col offset within W_gate (K=1024)

    // A tile: 64 rows x 8 chunks(16B) = 512 units / 256 thr = 2 each
    #pragma unroll
    for (int i = 0; i < 2; i++) {
        int u = tid + i * 256, r = u >> 3, cu = u & 7;
        cp16(stg + SWZ((uint32_t)(r * 128 + cu * 16)),
             xa + (m0 + r) * 512 + kloc + cu * 4);
    }
    // B tile: 192 rows x 8 chunks = 1536 units / 256 thr = 6 each
    const uint32_t bb = stg + A_BYTES;
    #pragma unroll
    for (int i = 0; i < 6; i++) {
        int u = tid + i * 256, r = u >> 3, cu = u & 7;
        const int ws = r / 48, rr = r - ws * 48;   // wn slice, row within slice
        const int un = n0 + ws * 16;
        const float* src;
        if (rr < 16)       src = Wg  + (un + rr) * 1024 + kg + cu * 4;        // r
        else if (rr < 32)  src = Wg  + (512 + un + rr - 16) * 1024 + kg + cu * 4; // z
        else               src = wih + (un + rr - 32) * 512 + kloc + cu * 4;  // ih
        cp16(bb + SWZ((uint32_t)(r * 128 + cu * 16)), src);
    }
}

template <bool PH>  // PH=false: kt<16 (i phase), PH=true: kt>=16 (h phase)
__device__ __forceinline__ void compute_tile(
    uint32_t Ab, uint32_t Bb, int wm, int wn, int lane,
    float (&alo)[2][6][4], float (&ahi)[2][2][4])
{
    const uint32_t arow = (uint32_t)(wm * 32 + (lane & 7) + ((lane >> 3) & 1) * 8);
    const uint32_t acb  = (uint32_t)((lane >> 4) * 16);
    const uint32_t brow = (uint32_t)(wn * 48 + ((lane >> 4) * 8) + (lane & 7));
    const uint32_t bcb  = (uint32_t)(((lane >> 3) & 1) * 16);

    #pragma unroll
    for (int ks = 0; ks < 4; ks++) {
        uint32_t a[2][4];
        #pragma unroll
        for (int mi = 0; mi < 2; mi++) {
            uint32_t off = (arow + mi * 16) * 128 + (uint32_t)(ks * 32) + acb;
            ldsm4(a[mi][0], a[mi][1], a[mi][2], a[mi][3], Ab + SWZ(off));
        }
        uint32_t b[6][2];
        #pragma unroll
        for (int p = 0; p < 3; p++) {
            uint32_t off = (brow + p * 16) * 128 + (uint32_t)(ks * 32) + bcb;
            ldsm4(b[2 * p][0], b[2 * p][1], b[2 * p + 1][0], b[2 * p + 1][1],
                  Bb + SWZ(off));
        }
        #pragma unroll
        for (int mi = 0; mi < 2; mi++) {
            #pragma unroll
            for (int nb = 0; nb < 6; nb++) {
                if (PH && nb >= 4)
                    mma8(ahi[mi][nb - 4], a[mi], b[nb][0], b[nb][1]);
                else
                    mma8(alo[mi][nb], a[mi], b[nb][0], b[nb][1]);
            }
        }
    }
}

__global__ void __launch_bounds__(256, 2)
gru_mma_kernel(const float* __restrict__ input, const float* __restrict__ hidden,
               const float* __restrict__ Wg, const float* __restrict__ bg,
               const float* __restrict__ Wi, const float* __restrict__ bi,
               const float* __restrict__ Wh, const float* __restrict__ bh,
               float* __restrict__ out)
{
    extern __shared__ char dsm[];
    const int tid  = threadIdx.x;
    const int lane = tid & 31;
    const int wid  = tid >> 5;
    const int wm   = wid >> 2;          // 0..1 (M)
    const int wn   = wid & 3;           // 0..3 (N slice)
    const int n0 = blockIdx.x * 64;     // hidden-unit slice
    const int m0 = blockIdx.y * 64;     // batch-row slice

    const uint32_t raw = smem_u32(dsm);
    const uint32_t sb  = (raw + 127u) & ~127u;
    char* gb = dsm + (sb - raw);

    // biases: br[64]@0, bz@64, bi@128, bh@192 (floats)
    float* sbias = (float*)gb;
    {
        int g = tid >> 6, j = tid & 63;
        float v;
        if (g == 0)      v = bg[n0 + j];
        else if (g == 1) v = bg[512 + n0 + j];
        else if (g == 2) v = bi[n0 + j];
        else             v = bh[n0 + j];
        sbias[tid] = v;
    }

    float alo[2][6][4];
    float ahi[2][2][4];
    #pragma unroll
    for (int mi = 0; mi < 2; mi++) {
        #pragma unroll
        for (int nb = 0; nb < 6; nb++)
            #pragma unroll
            for (int e = 0; e < 4; e++) alo[mi][nb][e] = 0.0f;
        #pragma unroll
        for (int nb = 0; nb < 2; nb++)
            #pragma unroll
            for (int e = 0; e < 4; e++) ahi[mi][nb][e] = 0.0f;
    }

    // prefetch stages 0..1
    #pragma unroll
    for (int p = 0; p < 2; p++) {
        fill_stage(p, sb + 1024 + (uint32_t)p * STAGE_BYTES, tid, m0, n0,
                   input, hidden, Wg, Wi, Wh);
        CP_COMMIT();
    }

    // One barrier per iter; fill(kt+2) overwrites the stage compute(kt-1)
    // used, which the barrier protects. LDGSTS issues before the 48 MMAs.
    #pragma unroll 1
    for (int kt = 0; kt < 32; kt++) {
        const int si = kt % 3;
        const uint32_t stg = sb + 1024 + (uint32_t)si * STAGE_BYTES;
        CP_WAIT(1);
        __syncthreads();
        if (kt + 2 < 32) {
            fill_stage(kt + 2, sb + 1024 + (uint32_t)((kt + 2) % 3) * STAGE_BYTES,
                       tid, m0, n0, input, hidden, Wg, Wi, Wh);
        }
        CP_COMMIT();   // empty group when no fill keeps accounting uniform
        if (kt < 16) compute_tile<false>(stg, stg + A_BYTES, wm, wn, lane, alo, ahi);
        else         compute_tile<true >(stg, stg + A_BYTES, wm, wn, lane, alo, ahi);
    }

    // ---- register-resident epilogue ----
    // Warp (wm,wn) owns rows wm*32..+31 and units wn*16..+15 for ALL gates:
    // nb 0,1 = r; nb 2,3 = z; nb 4,5 = i (alo) / h (ahi). Fragment element
    // (lane,e): row = wm*32+mi*16+lane/4 (+8 for e>=2), col = nb*8+2*(lane%4)+e&1.
    const float* sb_r = sbias;
    const float* sb_z = sbias + 64;
    const float* sb_i = sbias + 128;
    const float* sb_h = sbias + 192;

    #pragma unroll
    for (int mi = 0; mi < 2; mi++) {
        #pragma unroll
        for (int unb = 0; unb < 2; unb++) {
            const int uu = wn * 16 + unb * 8 + 2 * (lane & 3);   // unit (local)
            const float br0 = sb_r[uu], br1 = sb_r[uu + 1];
            const float bz0 = sb_z[uu], bz1 = sb_z[uu + 1];
            const float bi0 = sb_i[uu], bi1 = sb_i[uu + 1];
            const float bh0 = sb_h[uu], bh1 = sb_h[uu + 1];
            #pragma unroll
            for (int half = 0; half < 2; half++) {
                const int m = wm * 32 + mi * 16 + (lane >> 2) + 8 * half;
                const float rv0 = fsigmoid(alo[mi][0 + unb][2 * half]     + br0);
                const float rv1 = fsigmoid(alo[mi][0 + unb][2 * half + 1] + br1);
                const float zv0 = fsigmoid(alo[mi][2 + unb][2 * half]     + bz0);
                const float zv1 = fsigmoid(alo[mi][2 + unb][2 * half + 1] + bz1);
                const float iv0 = alo[mi][4 + unb][2 * half];
                const float iv1 = alo[mi][4 + unb][2 * half + 1];
                const float hv0 = ahi[mi][unb][2 * half];
                const float hv1 = ahi[mi][unb][2 * half + 1];
                const float2 hg = *(const float2*)&hidden[(m0 + m) * 512 + n0 + uu];
                const float ng0 = ftanh(iv0 + bi0 + rv0 * (hv0 + bh0));
                const float ng1 = ftanh(iv1 + bi1 + rv1 * (hv1 + bh1));
                float2 o;
                o.x = (1.0f - zv0) * ng0 + zv0 * hg.x;
                o.y = (1.0f - zv1) * ng1 + zv1 * hg.y;
                *(float2*)&out[(m0 + m) * 512 + n0 + uu] = o;
            }
        }
    }
}

extern "C" void kernel_launch(void* const* d_in, const int* in_sizes, int n_in,
                              void* d_out, int out_size)
{
    const float* input  = (const float*)d_in[0];
    const float* hidden = (const float*)d_in[1];
    const float* Wg     = (const float*)d_in[2];
    const float* bg     = (const float*)d_in[3];
    const float* Wi     = (const float*)d_in[4];
    const float* bi     = (const float*)d_in[5];
    const float* Wh     = (const float*)d_in[6];
    const float* bh     = (const float*)d_in[7];
    float* out = (float*)d_out;

    cudaFuncSetAttribute(gru_mma_kernel,
                         cudaFuncAttributeMaxDynamicSharedMemorySize, SMEM_BYTES);
    // grid.x = 8 n-slices (fast dim -> concurrent CTAs share X in L2),
    // grid.y = 256 batch tiles of 64 rows
    gru_mma_kernel<<<dim3(8, 256), 256, SMEM_BYTES>>>(
        input, hidden, Wg, bg, Wi, bi, Wh, bh, out);
}

// round 5
// speedup vs baseline: 1.1754x; 1.0797x over previous
#include <cuda_runtime.h>
#include <cstdint>

// ---------------------------------------------------------------------------
// Fused GRU cell via mma.sync tf32 (compute_103-safe PTX; no tcgen05/TMA).
// R5: strength-reduced addressing — persistent striding source pointers for
// cp.async, precomputed swizzled smem offsets, ks-XOR trick for LDSM addrs
// (SWZ(base + ks*32) == SWZ(base) ^ (ks<<5) when base bits 5-6 are zero).
//
// CTA tile M=64 x 192 B-rows, 2 CTAs/SM, warps 2(M)x4(N), per-wn slice
// [r:16|z:16|ih:16] -> register-resident epilogue.
// K loop: 32 tiles of BK=32 over X=[input|hidden] (K=1024). kt<16: ih rows
// hold Wi, accumulate alo (i). kt>=16: Wh, accumulate ahi (h).
// ---------------------------------------------------------------------------

#define SWZ(x) ((x) ^ (((x) >> 3) & 0x70))

__device__ __forceinline__ uint32_t smem_u32(const void* p) {
    uint32_t a;
    asm("{ .reg .u64 t; cvta.to.shared.u64 t, %1; cvt.u32.u64 %0, t; }"
        : "=r"(a) : "l"(p));
    return a;
}

__device__ __forceinline__ void cp16(uint32_t dst, const float* src) {
    asm volatile("cp.async.cg.shared.global [%0], [%1], 16;"
                 :: "r"(dst), "l"(src) : "memory");
}
#define CP_COMMIT() asm volatile("cp.async.commit_group;" ::: "memory")
#define CP_WAIT(n)  asm volatile("cp.async.wait_group %0;" :: "n"(n) : "memory")

__device__ __forceinline__ void ldsm4(uint32_t& r0, uint32_t& r1,
                                      uint32_t& r2, uint32_t& r3, uint32_t addr) {
    asm volatile("ldmatrix.sync.aligned.m8n8.x4.shared.b16 {%0,%1,%2,%3}, [%4];"
                 : "=r"(r0), "=r"(r1), "=r"(r2), "=r"(r3) : "r"(addr));
}

__device__ __forceinline__ void mma8(float* c, const uint32_t* a,
                                     uint32_t b0, uint32_t b1) {
    asm volatile(
        "mma.sync.aligned.m16n8k8.row.col.f32.tf32.tf32.f32 "
        "{%0,%1,%2,%3}, {%4,%5,%6,%7}, {%8,%9}, {%0,%1,%2,%3};"
        : "+f"(c[0]), "+f"(c[1]), "+f"(c[2]), "+f"(c[3])
        : "r"(a[0]), "r"(a[1]), "r"(a[2]), "r"(a[3]), "r"(b0), "r"(b1));
}

__device__ __forceinline__ float fsigmoid(float x) {
    return 1.0f / (1.0f + __expf(-x));
}
__device__ __forceinline__ float ftanh(float x) {
    float e = __expf(2.0f * x);          // overflow->inf, underflow->0: safe
    return 1.0f - 2.0f / (e + 1.0f);
}

// ---- geometry ----
static constexpr int NSTAGE      = 3;
static constexpr int A_BYTES     = 64 * 128;           // 64 rows x 32 fp32
static constexpr int B_BYTES     = 192 * 128;          // 192 rows x 32 fp32
static constexpr int STAGE_BYTES = A_BYTES + B_BYTES;  // 32768
static constexpr int SMEM_BYTES  = 1024 + 1024 + NSTAGE * STAGE_BYTES;

// (Re)initialize the 8 striding cp.async source pointers for a phase.
// phase 0: kt in [0,16)  -> xa=input,  wih=Wi, W_gate k-base 0
// phase 1: kt in [16,32) -> xa=hidden, wih=Wh, W_gate k-base 512
__device__ __forceinline__ void init_ptrs(
    int phase, int tid, int m0, int n0,
    const float* __restrict__ input, const float* __restrict__ hidden,
    const float* __restrict__ Wg, const float* __restrict__ Wi,
    const float* __restrict__ Wh,
    const float* (&pA)[2], const float* (&pB)[6])
{
    const float* xa  = phase ? hidden : input;
    const float* wih = phase ? Wh : Wi;
    const int kg = phase ? 512 : 0;
    #pragma unroll
    for (int i = 0; i < 2; i++) {
        int u = tid + i * 256, r = u >> 3, cu = u & 7;
        pA[i] = xa + (m0 + r) * 512 + cu * 4;
    }
    #pragma unroll
    for (int i = 0; i < 6; i++) {
        int u = tid + i * 256, r = u >> 3, cu = u & 7;
        const int ws = r / 48, rr = r - ws * 48;
        const int un = n0 + ws * 16;
        if (rr < 16)       pB[i] = Wg  + (un + rr) * 1024 + kg + cu * 4;
        else if (rr < 32)  pB[i] = Wg  + (512 + un + rr - 16) * 1024 + kg + cu * 4;
        else               pB[i] = wih + (un + rr - 32) * 512 + cu * 4;
    }
}

template <bool PH>  // PH=false: i phase (alo), PH=true: h phase (ahi)
__device__ __forceinline__ void compute_tile(
    uint32_t stg, const uint32_t (&aoff)[2], const uint32_t (&boff)[3],
    float (&alo)[2][6][4], float (&ahi)[2][2][4])
{
    #pragma unroll
    for (int ks = 0; ks < 4; ks++) {
        const uint32_t kx = (uint32_t)(ks << 5);
        uint32_t a[2][4];
        #pragma unroll
        for (int mi = 0; mi < 2; mi++)
            ldsm4(a[mi][0], a[mi][1], a[mi][2], a[mi][3], stg + (aoff[mi] ^ kx));
        uint32_t b[6][2];
        #pragma unroll
        for (int p = 0; p < 3; p++)
            ldsm4(b[2 * p][0], b[2 * p][1], b[2 * p + 1][0], b[2 * p + 1][1],
                  stg + (boff[p] ^ kx));
        #pragma unroll
        for (int mi = 0; mi < 2; mi++) {
            #pragma unroll
            for (int nb = 0; nb < 6; nb++) {
                if (PH && nb >= 4)
                    mma8(ahi[mi][nb - 4], a[mi], b[nb][0], b[nb][1]);
                else
                    mma8(alo[mi][nb], a[mi], b[nb][0], b[nb][1]);
            }
        }
    }
}

__global__ void __launch_bounds__(256, 2)
gru_mma_kernel(const float* __restrict__ input, const float* __restrict__ hidden,
               const float* __restrict__ Wg, const float* __restrict__ bg,
               const float* __restrict__ Wi, const float* __restrict__ bi,
               const float* __restrict__ Wh, const float* __restrict__ bh,
               float* __restrict__ out)
{
    extern __shared__ char dsm[];
    const int tid  = threadIdx.x;
    const int lane = tid & 31;
    const int wid  = tid >> 5;
    const int wm   = wid >> 2;          // 0..1 (M)
    const int wn   = wid & 3;           // 0..3 (N slice)
    const int n0 = blockIdx.x * 64;     // hidden-unit slice
    const int m0 = blockIdx.y * 64;     // batch-row slice

    const uint32_t raw = smem_u32(dsm);
    const uint32_t sb  = (raw + 1023u) & ~1023u;   // 1KB align for SW128
    char* gb = dsm + (sb - raw);
    const uint32_t stage0 = sb + 1024;

    // biases: br[64]@0, bz@64, bi@128, bh@192 (floats)
    float* sbias = (float*)gb;
    {
        int g = tid >> 6, j = tid & 63;
        float v;
        if (g == 0)      v = bg[n0 + j];
        else if (g == 1) v = bg[512 + n0 + j];
        else if (g == 2) v = bi[n0 + j];
        else             v = bh[n0 + j];
        sbias[tid] = v;
    }

    // ---- persistent fill state: smem offsets (stage-invariant) + src ptrs ----
    uint32_t fA[2], fB[6];
    #pragma unroll
    for (int i = 0; i < 2; i++) {
        int u = tid + i * 256, r = u >> 3, cu = u & 7;
        fA[i] = SWZ((uint32_t)(r * 128 + cu * 16));
    }
    #pragma unroll
    for (int i = 0; i < 6; i++) {
        int u = tid + i * 256, r = u >> 3, cu = u & 7;
        fB[i] = (uint32_t)A_BYTES + SWZ((uint32_t)(r * 128 + cu * 16));
    }
    const float* pA[2];
    const float* pB[6];
    init_ptrs(0, tid, m0, n0, input, hidden, Wg, Wi, Wh, pA, pB);

    // ---- LDSM swizzled base offsets (ks enters via XOR of bits 5-6) ----
    uint32_t aoff[2], boff[3];
    {
        const uint32_t arow = (uint32_t)(wm * 32 + (lane & 7) + ((lane >> 3) & 1) * 8);
        const uint32_t acb  = (uint32_t)((lane >> 4) * 16);
        const uint32_t brow = (uint32_t)(wn * 48 + ((lane >> 4) * 8) + (lane & 7));
        const uint32_t bcb  = (uint32_t)(((lane >> 3) & 1) * 16);
        #pragma unroll
        for (int mi = 0; mi < 2; mi++)
            aoff[mi] = SWZ((arow + mi * 16) * 128 + acb);
        #pragma unroll
        for (int p = 0; p < 3; p++)
            boff[p] = (uint32_t)A_BYTES + SWZ((brow + p * 16) * 128 + bcb);
    }

    float alo[2][6][4];
    float ahi[2][2][4];
    #pragma unroll
    for (int mi = 0; mi < 2; mi++) {
        #pragma unroll
        for (int nb = 0; nb < 6; nb++)
            #pragma unroll
            for (int e = 0; e < 4; e++) alo[mi][nb][e] = 0.0f;
        #pragma unroll
        for (int nb = 0; nb < 2; nb++)
            #pragma unroll
            for (int e = 0; e < 4; e++) ahi[mi][nb][e] = 0.0f;
    }

    // prefetch fills f=0,1
    #pragma unroll
    for (int f = 0; f < 2; f++) {
        const uint32_t stg = stage0 + (uint32_t)f * STAGE_BYTES;
        #pragma unroll
        for (int i = 0; i < 2; i++) { cp16(stg + fA[i], pA[i]); pA[i] += 32; }
        #pragma unroll
        for (int i = 0; i < 6; i++) { cp16(stg + fB[i], pB[i]); pB[i] += 32; }
        CP_COMMIT();
    }

    // One barrier per iter; fill(kt+2) overwrites the stage compute(kt-1)
    // used, which the barrier protects. LDGSTS issues before the 48 MMAs.
    #pragma unroll 1
    for (int kt = 0; kt < 32; kt++) {
        const uint32_t stg = stage0 + (uint32_t)(kt % 3) * STAGE_BYTES;
        CP_WAIT(1);
        __syncthreads();
        const int f = kt + 2;
        if (f == 16)   // phase switch for fills: input->hidden, Wi->Wh, kg 0->512
            init_ptrs(1, tid, m0, n0, input, hidden, Wg, Wi, Wh, pA, pB);
        if (f < 32) {
            const uint32_t fst = stage0 + (uint32_t)(f % 3) * STAGE_BYTES;
            #pragma unroll
            for (int i = 0; i < 2; i++) { cp16(fst + fA[i], pA[i]); pA[i] += 32; }
            #pragma unroll
            for (int i = 0; i < 6; i++) { cp16(fst + fB[i], pB[i]); pB[i] += 32; }
        }
        CP_COMMIT();   // empty group when no fill keeps accounting uniform
        if (kt < 16) compute_tile<false>(stg, aoff, boff, alo, ahi);
        else         compute_tile<true >(stg, aoff, boff, alo, ahi);
    }

    // ---- register-resident epilogue ----
    // Warp (wm,wn) owns rows wm*32..+31 and units wn*16..+15 for ALL gates:
    // nb 0,1 = r; nb 2,3 = z; nb 4,5 = i (alo) / h (ahi).
    const float* sb_r = sbias;
    const float* sb_z = sbias + 64;
    const float* sb_i = sbias + 128;
    const float* sb_h = sbias + 192;

    #pragma unroll
    for (int mi = 0; mi < 2; mi++) {
        #pragma unroll
        for (int unb = 0; unb < 2; unb++) {
            const int uu = wn * 16 + unb * 8 + 2 * (lane & 3);   // unit (local)
            const float br0 = sb_r[uu], br1 = sb_r[uu + 1];
            const float bz0 = sb_z[uu], bz1 = sb_z[uu + 1];
            const float bi0 = sb_i[uu], bi1 = sb_i[uu + 1];
            const float bh0 = sb_h[uu], bh1 = sb_h[uu + 1];
            #pragma unroll
            for (int half = 0; half < 2; half++) {
                const int m = wm * 32 + mi * 16 + (lane >> 2) + 8 * half;
                const float rv0 = fsigmoid(alo[mi][0 + unb][2 * half]     + br0);
                const float rv1 = fsigmoid(alo[mi][0 + unb][2 * half + 1] + br1);
                const float zv0 = fsigmoid(alo[mi][2 + unb][2 * half]     + bz0);
                const float zv1 = fsigmoid(alo[mi][2 + unb][2 * half + 1] + bz1);
                const float iv0 = alo[mi][4 + unb][2 * half];
                const float iv1 = alo[mi][4 + unb][2 * half + 1];
                const float hv0 = ahi[mi][unb][2 * half];
                const float hv1 = ahi[mi][unb][2 * half + 1];
                const float2 hg = *(const float2*)&hidden[(m0 + m) * 512 + n0 + uu];
                const float ng0 = ftanh(iv0 + bi0 + rv0 * (hv0 + bh0));
                const float ng1 = ftanh(iv1 + bi1 + rv1 * (hv1 + bh1));
                float2 o;
                o.x = (1.0f - zv0) * ng0 + zv0 * hg.x;
                o.y = (1.0f - zv1) * ng1 + zv1 * hg.y;
                *(float2*)&out[(m0 + m) * 512 + n0 + uu] = o;
            }
        }
    }
}

extern "C" void kernel_launch(void* const* d_in, const int* in_sizes, int n_in,
                              void* d_out, int out_size)
{
    const float* input  = (const float*)d_in[0];
    const float* hidden = (const float*)d_in[1];
    const float* Wg     = (const float*)d_in[2];
    const float* bg     = (const float*)d_in[3];
    const float* Wi     = (const float*)d_in[4];
    const float* bi     = (const float*)d_in[5];
    const float* Wh     = (const float*)d_in[6];
    const float* bh     = (const float*)d_in[7];
    float* out = (float*)d_out;

    cudaFuncSetAttribute(gru_mma_kernel,
                         cudaFuncAttributeMaxDynamicSharedMemorySize, SMEM_BYTES);
    // grid.x = 8 n-slices (fast dim -> concurrent CTAs share X in L2),
    // grid.y = 256 batch tiles of 64 rows
    gru_mma_kernel<<<dim3(8, 256), 256, SMEM_BYTES>>>(
        input, hidden, Wg, bg, Wi, bi, Wh, bh, out);
}

// round 6
// speedup vs baseline: 1.1898x; 1.0123x over previous
#include <cuda_runtime.h>
#include <cstdint>
#include <cstddef>

// ---------------------------------------------------------------------------
// Fused GRU cell via mma.sync tf32 (compute_103-safe PTX; no tcgen05/TMA).
// R6: 2-stage pipeline (stage = kt&1, compile-time addresses via unroll-2
// phase-split loops), fill depth 1, pointer continuation across the k=512
// phase switch (W_gate strides straight through; xa/wih get one delta add).
//
// CTA tile M=64 x 192 B-rows, 2 CTAs/SM, warps 2(M)x4(N), per-wn slice
// [r:16|z:16|ih:16] -> register-resident epilogue.
// K loop: 32 tiles of BK=32 over X=[input|hidden] (K=1024). kt<16: ih rows
// hold Wi, accumulate alo (i). kt>=16: Wh, accumulate ahi (h).
// ---------------------------------------------------------------------------

#define SWZ(x) ((x) ^ (((x) >> 3) & 0x70))

__device__ __forceinline__ uint32_t smem_u32(const void* p) {
    uint32_t a;
    asm("{ .reg .u64 t; cvta.to.shared.u64 t, %1; cvt.u32.u64 %0, t; }"
        : "=r"(a) : "l"(p));
    return a;
}

__device__ __forceinline__ void cp16(uint32_t dst, const float* src) {
    asm volatile("cp.async.cg.shared.global [%0], [%1], 16;"
                 :: "r"(dst), "l"(src) : "memory");
}
#define CP_COMMIT() asm volatile("cp.async.commit_group;" ::: "memory")
#define CP_WAIT0()  asm volatile("cp.async.wait_group 0;" ::: "memory")

__device__ __forceinline__ void ldsm4(uint32_t& r0, uint32_t& r1,
                                      uint32_t& r2, uint32_t& r3, uint32_t addr) {
    asm volatile("ldmatrix.sync.aligned.m8n8.x4.shared.b16 {%0,%1,%2,%3}, [%4];"
                 : "=r"(r0), "=r"(r1), "=r"(r2), "=r"(r3) : "r"(addr));
}

__device__ __forceinline__ void mma8(float* c, const uint32_t* a,
                                     uint32_t b0, uint32_t b1) {
    asm volatile(
        "mma.sync.aligned.m16n8k8.row.col.f32.tf32.tf32.f32 "
        "{%0,%1,%2,%3}, {%4,%5,%6,%7}, {%8,%9}, {%0,%1,%2,%3};"
        : "+f"(c[0]), "+f"(c[1]), "+f"(c[2]), "+f"(c[3])
        : "r"(a[0]), "r"(a[1]), "r"(a[2]), "r"(a[3]), "r"(b0), "r"(b1));
}

__device__ __forceinline__ float fsigmoid(float x) {
    return 1.0f / (1.0f + __expf(-x));
}
__device__ __forceinline__ float ftanh(float x) {
    float e = __expf(2.0f * x);          // overflow->inf, underflow->0: safe
    return 1.0f - 2.0f / (e + 1.0f);
}

// ---- geometry ----
static constexpr int A_BYTES     = 64 * 128;           // 64 rows x 32 fp32
static constexpr int B_BYTES     = 192 * 128;          // 192 rows x 32 fp32
static constexpr int STAGE_BYTES = A_BYTES + B_BYTES;  // 32768
static constexpr int SMEM_BYTES  = 1024 + 1024 + 2 * STAGE_BYTES;  // ~67.5KB

template <bool PH>  // PH=false: i phase (alo), PH=true: h phase (ahi)
__device__ __forceinline__ void compute_tile(
    uint32_t stg, const uint32_t (&aoff)[2], const uint32_t (&boff)[3],
    float (&alo)[2][6][4], float (&ahi)[2][2][4])
{
    #pragma unroll
    for (int ks = 0; ks < 4; ks++) {
        const uint32_t kx = (uint32_t)(ks << 5);
        uint32_t a[2][4];
        #pragma unroll
        for (int mi = 0; mi < 2; mi++)
            ldsm4(a[mi][0], a[mi][1], a[mi][2], a[mi][3], stg + (aoff[mi] ^ kx));
        uint32_t b[6][2];
        #pragma unroll
        for (int p = 0; p < 3; p++)
            ldsm4(b[2 * p][0], b[2 * p][1], b[2 * p + 1][0], b[2 * p + 1][1],
                  stg + (boff[p] ^ kx));
        #pragma unroll
        for (int mi = 0; mi < 2; mi++) {
            #pragma unroll
            for (int nb = 0; nb < 6; nb++) {
                if (PH && nb >= 4)
                    mma8(ahi[mi][nb - 4], a[mi], b[nb][0], b[nb][1]);
                else
                    mma8(alo[mi][nb], a[mi], b[nb][0], b[nb][1]);
            }
        }
    }
}

__global__ void __launch_bounds__(256, 2)
gru_mma_kernel(const float* __restrict__ input, const float* __restrict__ hidden,
               const float* __restrict__ Wg, const float* __restrict__ bg,
               const float* __restrict__ Wi, const float* __restrict__ bi,
               const float* __restrict__ Wh, const float* __restrict__ bh,
               float* __restrict__ out)
{
    extern __shared__ char dsm[];
    const int tid  = threadIdx.x;
    const int lane = tid & 31;
    const int wid  = tid >> 5;
    const int wm   = wid >> 2;          // 0..1 (M)
    const int wn   = wid & 3;           // 0..3 (N slice)
    const int n0 = blockIdx.x * 64;     // hidden-unit slice
    const int m0 = blockIdx.y * 64;     // batch-row slice

    const uint32_t raw = smem_u32(dsm);
    const uint32_t sb  = (raw + 1023u) & ~1023u;   // 1KB align for SW128
    char* gb = dsm + (sb - raw);
    const uint32_t stage0 = sb + 1024;
    const uint32_t stage1 = stage0 + STAGE_BYTES;

    // biases: br[64]@0, bz@64, bi@128, bh@192 (floats)
    float* sbias = (float*)gb;
    {
        int g = tid >> 6, j = tid & 63;
        float v;
        if (g == 0)      v = bg[n0 + j];
        else if (g == 1) v = bg[512 + n0 + j];
        else if (g == 2) v = bi[n0 + j];
        else             v = bh[n0 + j];
        sbias[tid] = v;
    }

    // ---- persistent fill state ----
    // smem offsets (stage-invariant), striding source pointers, phase deltas.
    uint32_t fA[2], fB[6];
    const float* pA[2];
    const float* pB[6];
    bool isw[6];   // pB[i] points into Wi/Wh (needs delta at phase switch)
    #pragma unroll
    for (int i = 0; i < 2; i++) {
        int u = tid + i * 256, r = u >> 3, cu = u & 7;
        fA[i] = SWZ((uint32_t)(r * 128 + cu * 16));
        pA[i] = input + (m0 + r) * 512 + cu * 4;
    }
    #pragma unroll
    for (int i = 0; i < 6; i++) {
        int u = tid + i * 256, r = u >> 3, cu = u & 7;
        fB[i] = (uint32_t)A_BYTES + SWZ((uint32_t)(r * 128 + cu * 16));
        const int ws = r / 48, rr = r - ws * 48;
        const int un = n0 + ws * 16;
        isw[i] = (rr >= 32);
        if (rr < 16)       pB[i] = Wg + (un + rr) * 1024 + cu * 4;
        else if (rr < 32)  pB[i] = Wg + (512 + un + rr - 16) * 1024 + cu * 4;
        else               pB[i] = Wi + (un + rr - 32) * 512 + cu * 4;
    }
    // Phase-switch deltas: after 16 strides of +32, xa ptr = input+row*512+512+c;
    // want hidden+row*512+c. W_gate continues through k=512 with no reset.
    const ptrdiff_t dxa = (hidden - input) - 512;
    const ptrdiff_t dwh = (Wh - Wi) - 512;

    // ---- LDSM swizzled base offsets (ks enters via XOR of bits 5-6) ----
    uint32_t aoff[2], boff[3];
    {
        const uint32_t arow = (uint32_t)(wm * 32 + (lane & 7) + ((lane >> 3) & 1) * 8);
        const uint32_t acb  = (uint32_t)((lane >> 4) * 16);
        const uint32_t brow = (uint32_t)(wn * 48 + ((lane >> 4) * 8) + (lane & 7));
        const uint32_t bcb  = (uint32_t)(((lane >> 3) & 1) * 16);
        #pragma unroll
        for (int mi = 0; mi < 2; mi++)
            aoff[mi] = SWZ((arow + mi * 16) * 128 + acb);
        #pragma unroll
        for (int p = 0; p < 3; p++)
            boff[p] = (uint32_t)A_BYTES + SWZ((brow + p * 16) * 128 + bcb);
    }

    float alo[2][6][4];
    float ahi[2][2][4];
    #pragma unroll
    for (int mi = 0; mi < 2; mi++) {
        #pragma unroll
        for (int nb = 0; nb < 6; nb++)
            #pragma unroll
            for (int e = 0; e < 4; e++) alo[mi][nb][e] = 0.0f;
        #pragma unroll
        for (int nb = 0; nb < 2; nb++)
            #pragma unroll
            for (int e = 0; e < 4; e++) ahi[mi][nb][e] = 0.0f;
    }

    // fill helper (macro-ish lambda; stage address is a compile-time-selected reg)
    auto do_fill = [&](uint32_t stg) {
        #pragma unroll
        for (int i = 0; i < 2; i++) { cp16(stg + fA[i], pA[i]); pA[i] += 32; }
        #pragma unroll
        for (int i = 0; i < 6; i++) { cp16(stg + fB[i], pB[i]); pB[i] += 32; }
        CP_COMMIT();
    };

    // prologue: fill stage0 for kt=0
    do_fill(stage0);

    // Phase 0: kt = 0..15. Barrier protects WAR on the stage being refilled
    // (all warps finished compute(kt-1) on stage (kt+1)&1) and makes fill(kt)
    // visible CTA-wide after CP_WAIT0.
    #pragma unroll 2
    for (int kt = 0; kt < 16; kt++) {
        const uint32_t stg = (kt & 1) ? stage1 : stage0;
        CP_WAIT0();
        __syncthreads();
        if (kt == 15) {   // next fill is f=16: switch xa->hidden, Wi->Wh
            pA[0] += dxa; pA[1] += dxa;
            #pragma unroll
            for (int i = 0; i < 6; i++) if (isw[i]) pB[i] += dwh;
        }
        do_fill((kt & 1) ? stage0 : stage1);
        compute_tile<false>(stg, aoff, boff, alo, ahi);
    }
    // Phase 1: kt = 16..31.
    #pragma unroll 2
    for (int kt = 16; kt < 32; kt++) {
        const uint32_t stg = (kt & 1) ? stage1 : stage0;
        CP_WAIT0();
        __syncthreads();
        if (kt < 31) do_fill((kt & 1) ? stage0 : stage1);
        compute_tile<true>(stg, aoff, boff, alo, ahi);
    }

    // ---- register-resident epilogue ----
    // Warp (wm,wn) owns rows wm*32..+31 and units wn*16..+15 for ALL gates:
    // nb 0,1 = r; nb 2,3 = z; nb 4,5 = i (alo) / h (ahi).
    const float* sb_r = sbias;
    const float* sb_z = sbias + 64;
    const float* sb_i = sbias + 128;
    const float* sb_h = sbias + 192;

    #pragma unroll
    for (int mi = 0; mi < 2; mi++) {
        #pragma unroll
        for (int unb = 0; unb < 2; unb++) {
            const int uu = wn * 16 + unb * 8 + 2 * (lane & 3);   // unit (local)
            const float br0 = sb_r[uu], br1 = sb_r[uu + 1];
            const float bz0 = sb_z[uu], bz1 = sb_z[uu + 1];
            const float bi0 = sb_i[uu], bi1 = sb_i[uu + 1];
            const float bh0 = sb_h[uu], bh1 = sb_h[uu + 1];
            #pragma unroll
            for (int half = 0; half < 2; half++) {
                const int m = wm * 32 + mi * 16 + (lane >> 2) + 8 * half;
                const float rv0 = fsigmoid(alo[mi][0 + unb][2 * half]     + br0);
                const float rv1 = fsigmoid(alo[mi][0 + unb][2 * half + 1] + br1);
                const float zv0 = fsigmoid(alo[mi][2 + unb][2 * half]     + bz0);
                const float zv1 = fsigmoid(alo[mi][2 + unb][2 * half + 1] + bz1);
                const float iv0 = alo[mi][4 + unb][2 * half];
                const float iv1 = alo[mi][4 + unb][2 * half + 1];
                const float hv0 = ahi[mi][unb][2 * half];
                const float hv1 = ahi[mi][unb][2 * half + 1];
                const float2 hg = *(const float2*)&hidden[(m0 + m) * 512 + n0 + uu];
                const float ng0 = ftanh(iv0 + bi0 + rv0 * (hv0 + bh0));
                const float ng1 = ftanh(iv1 + bi1 + rv1 * (hv1 + bh1));
                float2 o;
                o.x = (1.0f - zv0) * ng0 + zv0 * hg.x;
                o.y = (1.0f - zv1) * ng1 + zv1 * hg.y;
                *(float2*)&out[(m0 + m) * 512 + n0 + uu] = o;
            }
        }
    }
}

extern "C" void kernel_launch(void* const* d_in, const int* in_sizes, int n_in,
                              void* d_out, int out_size)
{
    const float* input  = (const float*)d_in[0];
    const float* hidden = (const float*)d_in[1];
    const float* Wg     = (const float*)d_in[2];
    const float* bg     = (const float*)d_in[3];
    const float* Wi     = (const float*)d_in[4];
    const float* bi     = (const float*)d_in[5];
    const float* Wh     = (const float*)d_in[6];
    const float* bh     = (const float*)d_in[7];
    float* out = (float*)d_out;

    cudaFuncSetAttribute(gru_mma_kernel,
                         cudaFuncAttributeMaxDynamicSharedMemorySize, SMEM_BYTES);
    // grid.x = 8 n-slices (fast dim -> concurrent CTAs share X in L2),
    // grid.y = 256 batch tiles of 64 rows
    gru_mma_kernel<<<dim3(8, 256), 256, SMEM_BYTES>>>(
        input, hidden, Wg, bg, Wi, bi, Wh, bh, out);
}

// round 7
// speedup vs baseline: 1.2053x; 1.0130x over previous
#include <cuda_runtime.h>
#include <cstdint>
#include <cstddef>

// ---------------------------------------------------------------------------
// Fused GRU cell via mma.sync tf32 (compute_103-safe PTX; no tcgen05/TMA).
// R7: BK=64 (16 k-iters, half the barriers), one 512-thread CTA/SM,
// M=128 x 64 units, pitch-256 rows with per-128B-half SW128 swizzle.
// LDSM addr = base ^ (ks<<5) for ks 0..7 (bit 7 = half select, 0 in base).
//
// B operand rows (192), per wn slice s = wn*48:
//   rows [s+ 0,s+16): W_gate[n0+wn*16+u]     -> r (nb 0,1)
//   rows [s+16,s+32): W_gate[512+n0+wn*16+u] -> z (nb 2,3)
//   rows [s+32,s+48): Wi/Wh[n0+wn*16+u]      -> i/h (nb 4,5, phase split)
// kt<8: X=input, ih=Wi -> alo. kt>=8: X=hidden, ih=Wh -> ahi.
// ---------------------------------------------------------------------------

__device__ __forceinline__ uint32_t smem_u32(const void* p) {
    uint32_t a;
    asm("{ .reg .u64 t; cvta.to.shared.u64 t, %1; cvt.u32.u64 %0, t; }"
        : "=r"(a) : "l"(p));
    return a;
}

__device__ __forceinline__ void cp16(uint32_t dst, const float* src) {
    asm volatile("cp.async.cg.shared.global [%0], [%1], 16;"
                 :: "r"(dst), "l"(src) : "memory");
}
#define CP_COMMIT() asm volatile("cp.async.commit_group;" ::: "memory")
#define CP_WAIT0()  asm volatile("cp.async.wait_group 0;" ::: "memory")

__device__ __forceinline__ void ldsm4(uint32_t& r0, uint32_t& r1,
                                      uint32_t& r2, uint32_t& r3, uint32_t addr) {
    asm volatile("ldmatrix.sync.aligned.m8n8.x4.shared.b16 {%0,%1,%2,%3}, [%4];"
                 : "=r"(r0), "=r"(r1), "=r"(r2), "=r"(r3) : "r"(addr));
}

__device__ __forceinline__ void mma8(float* c, const uint32_t* a,
                                     uint32_t b0, uint32_t b1) {
    asm volatile(
        "mma.sync.aligned.m16n8k8.row.col.f32.tf32.tf32.f32 "
        "{%0,%1,%2,%3}, {%4,%5,%6,%7}, {%8,%9}, {%0,%1,%2,%3};"
        : "+f"(c[0]), "+f"(c[1]), "+f"(c[2]), "+f"(c[3])
        : "r"(a[0]), "r"(a[1]), "r"(a[2]), "r"(a[3]), "r"(b0), "r"(b1));
}

__device__ __forceinline__ float fsigmoid(float x) {
    return 1.0f / (1.0f + __expf(-x));
}
__device__ __forceinline__ float ftanh(float x) {
    float e = __expf(2.0f * x);          // overflow->inf, underflow->0: safe
    return 1.0f - 2.0f / (e + 1.0f);
}

// ---- geometry ----
// Rows are 256B (64 tf32). Physical offset of (row, col byte c):
//   row*256 + (c>>7)*128 + ((c&127) ^ ((row&7)<<4))   [SW128 per 128B half]
static constexpr int A_BYTES     = 128 * 256;          // 32KB: 128 rows x 64 fp32
static constexpr int B_BYTES     = 192 * 256;          // 48KB
static constexpr int STAGE_BYTES = A_BYTES + B_BYTES;  // 81920
static constexpr int SMEM_BYTES  = 1024 + 1024 + 2 * STAGE_BYTES;  // ~162KB

// fill offset for 16B-chunk index u (u = tid + i*512; +8192 per i since
// row+32 preserves row&7)
__device__ __forceinline__ uint32_t fill_off(int u) {
    const int r = u >> 4, cu = u & 15;
    return (uint32_t)(r * 256 + ((cu >> 3) << 7) + (((cu & 7) * 16) ^ ((r & 7) << 4)));
}

template <bool PH>  // PH=false: i phase (alo), PH=true: h phase (ahi)
__device__ __forceinline__ void compute_tile(
    uint32_t stg, uint32_t aoff0, uint32_t boff0,
    float (&alo)[2][6][4], float (&ahi)[2][2][4])
{
    #pragma unroll
    for (int ks = 0; ks < 8; ks++) {
        const uint32_t kx = (uint32_t)(ks << 5);
        uint32_t a[2][4];
        #pragma unroll
        for (int mi = 0; mi < 2; mi++)
            ldsm4(a[mi][0], a[mi][1], a[mi][2], a[mi][3],
                  stg + (aoff0 ^ kx) + mi * 4096);
        uint32_t b[6][2];
        #pragma unroll
        for (int p = 0; p < 3; p++)
            ldsm4(b[2 * p][0], b[2 * p][1], b[2 * p + 1][0], b[2 * p + 1][1],
                  stg + (boff0 ^ kx) + p * 4096);
        #pragma unroll
        for (int mi = 0; mi < 2; mi++) {
            #pragma unroll
            for (int nb = 0; nb < 6; nb++) {
                if (PH && nb >= 4)
                    mma8(ahi[mi][nb - 4], a[mi], b[nb][0], b[nb][1]);
                else
                    mma8(alo[mi][nb], a[mi], b[nb][0], b[nb][1]);
            }
        }
    }
}

__global__ void __launch_bounds__(512, 1)
gru_mma_kernel(const float* __restrict__ input, const float* __restrict__ hidden,
               const float* __restrict__ Wg, const float* __restrict__ bg,
               const float* __restrict__ Wi, const float* __restrict__ bi,
               const float* __restrict__ Wh, const float* __restrict__ bh,
               float* __restrict__ out)
{
    extern __shared__ char dsm[];
    const int tid  = threadIdx.x;
    const int lane = tid & 31;
    const int wid  = tid >> 5;
    const int wm   = wid >> 2;          // 0..3 (M, 32 rows each)
    const int wn   = wid & 3;           // 0..3 (N slice, 16 units each)
    const int n0 = blockIdx.x * 64;     // hidden-unit slice
    const int m0 = blockIdx.y * 128;    // batch-row slice

    const uint32_t raw = smem_u32(dsm);
    const uint32_t sb  = (raw + 1023u) & ~1023u;
    char* gb = dsm + (sb - raw);
    const uint32_t stage0 = sb + 1024;
    const uint32_t stage1 = stage0 + STAGE_BYTES;

    // biases: br[64]@0, bz@64, bi@128, bh@192 (floats)
    float* sbias = (float*)gb;
    if (tid < 256) {
        int g = tid >> 6, j = tid & 63;
        float v;
        if (g == 0)      v = bg[n0 + j];
        else if (g == 1) v = bg[512 + n0 + j];
        else if (g == 2) v = bi[n0 + j];
        else             v = bh[n0 + j];
        sbias[tid] = v;
    }

    // ---- fill state ----
    const uint32_t fA0 = fill_off(tid);                        // + i*8192
    const uint32_t fB0 = (uint32_t)A_BYTES + fill_off(tid);    // + i*8192
    const int frow = tid >> 4, fcu = (tid & 15) * 4;
    const float* pA0 = input + (m0 + frow) * 512 + fcu;        // + i*16384
    const float* pB[6];
    bool isw[6];
    #pragma unroll
    for (int i = 0; i < 6; i++) {
        const int r = frow + 32 * i;
        const int ws = r / 48, rr = r - ws * 48;
        const int un = n0 + ws * 16;
        isw[i] = (rr >= 32);
        if (rr < 16)       pB[i] = Wg + (un + rr) * 1024 + fcu;
        else if (rr < 32)  pB[i] = Wg + (512 + un + rr - 16) * 1024 + fcu;
        else               pB[i] = Wi + (un + rr - 32) * 512 + fcu;
    }
    // Phase switch (after 8 fills of +64): xa ptr = input+row*512+512 ->
    // hidden+row*512. W_gate strides straight through k=512.
    const ptrdiff_t dxa = (hidden - input) - 512;
    const ptrdiff_t dwh = (Wh - Wi) - 512;

    // ---- LDSM base offsets ----
    uint32_t aoff0, boff0;
    {
        const uint32_t arow = (uint32_t)(wm * 32 + (lane & 7) + ((lane >> 3) & 1) * 8);
        const uint32_t acb  = (uint32_t)((lane >> 4) * 16);
        const uint32_t brow = (uint32_t)(wn * 48 + ((lane >> 4) * 8) + (lane & 7));
        const uint32_t bcb  = (uint32_t)(((lane >> 3) & 1) * 16);
        aoff0 = arow * 256 + (acb ^ ((arow & 7) << 4));                    // + mi*4096
        boff0 = (uint32_t)A_BYTES + brow * 256 + (bcb ^ ((brow & 7) << 4)); // + p*4096
    }

    float alo[2][6][4];
    float ahi[2][2][4];
    #pragma unroll
    for (int mi = 0; mi < 2; mi++) {
        #pragma unroll
        for (int nb = 0; nb < 6; nb++)
            #pragma unroll
            for (int e = 0; e < 4; e++) alo[mi][nb][e] = 0.0f;
        #pragma unroll
        for (int nb = 0; nb < 2; nb++)
            #pragma unroll
            for (int e = 0; e < 4; e++) ahi[mi][nb][e] = 0.0f;
    }

    auto do_fill = [&](uint32_t stg) {
        #pragma unroll
        for (int i = 0; i < 4; i++)
            cp16(stg + fA0 + (uint32_t)i * 8192u, pA0 + i * 16384);
        pA0 += 64;
        #pragma unroll
        for (int i = 0; i < 6; i++) {
            cp16(stg + fB0 + (uint32_t)i * 8192u, pB[i]);
            pB[i] += 64;
        }
        CP_COMMIT();
    };

    // prologue
    do_fill(stage0);

    // Phase 0: kt = 0..7 (X=input, ih=Wi -> alo)
    #pragma unroll 2
    for (int kt = 0; kt < 8; kt++) {
        const uint32_t stg = (kt & 1) ? stage1 : stage0;
        CP_WAIT0();
        __syncthreads();
        if (kt == 7) {   // next fill f=8: switch xa->hidden, Wi->Wh
            pA0 += dxa;
            #pragma unroll
            for (int i = 0; i < 6; i++) if (isw[i]) pB[i] += dwh;
        }
        do_fill((kt & 1) ? stage0 : stage1);
        compute_tile<false>(stg, aoff0, boff0, alo, ahi);
    }
    // Phase 1: kt = 8..15 (X=hidden, ih=Wh -> ahi)
    #pragma unroll 2
    for (int kt = 8; kt < 16; kt++) {
        const uint32_t stg = (kt & 1) ? stage1 : stage0;
        CP_WAIT0();
        __syncthreads();
        if (kt < 15) do_fill((kt & 1) ? stage0 : stage1);
        compute_tile<true>(stg, aoff0, boff0, alo, ahi);
    }

    // ---- register-resident epilogue ----
    // Warp (wm,wn) owns rows wm*32..+31 and units wn*16..+15 for ALL gates:
    // nb 0,1 = r; nb 2,3 = z; nb 4,5 = i (alo) / h (ahi).
    const float* sb_r = sbias;
    const float* sb_z = sbias + 64;
    const float* sb_i = sbias + 128;
    const float* sb_h = sbias + 192;

    #pragma unroll
    for (int mi = 0; mi < 2; mi++) {
        #pragma unroll
        for (int unb = 0; unb < 2; unb++) {
            const int uu = wn * 16 + unb * 8 + 2 * (lane & 3);   // unit (local)
            const float br0 = sb_r[uu], br1 = sb_r[uu + 1];
            const float bz0 = sb_z[uu], bz1 = sb_z[uu + 1];
            const float bi0 = sb_i[uu], bi1 = sb_i[uu + 1];
            const float bh0 = sb_h[uu], bh1 = sb_h[uu + 1];
            #pragma unroll
            for (int half = 0; half < 2; half++) {
                const int m = wm * 32 + mi * 16 + (lane >> 2) + 8 * half;
                const float rv0 = fsigmoid(alo[mi][0 + unb][2 * half]     + br0);
                const float rv1 = fsigmoid(alo[mi][0 + unb][2 * half + 1] + br1);
                const float zv0 = fsigmoid(alo[mi][2 + unb][2 * half]     + bz0);
                const float zv1 = fsigmoid(alo[mi][2 + unb][2 * half + 1] + bz1);
                const float iv0 = alo[mi][4 + unb][2 * half];
                const float iv1 = alo[mi][4 + unb][2 * half + 1];
                const float hv0 = ahi[mi][unb][2 * half];
                const float hv1 = ahi[mi][unb][2 * half + 1];
                const float2 hg = *(const float2*)&hidden[(m0 + m) * 512 + n0 + uu];
                const float ng0 = ftanh(iv0 + bi0 + rv0 * (hv0 + bh0));
                const float ng1 = ftanh(iv1 + bi1 + rv1 * (hv1 + bh1));
                float2 o;
                o.x = (1.0f - zv0) * ng0 + zv0 * hg.x;
                o.y = (1.0f - zv1) * ng1 + zv1 * hg.y;
                *(float2*)&out[(m0 + m) * 512 + n0 + uu] = o;
            }
        }
    }
}

extern "C" void kernel_launch(void* const* d_in, const int* in_sizes, int n_in,
                              void* d_out, int out_size)
{
    const float* input  = (const float*)d_in[0];
    const float* hidden = (const float*)d_in[1];
    const float* Wg     = (const float*)d_in[2];
    const float* bg     = (const float*)d_in[3];
    const float* Wi     = (const float*)d_in[4];
    const float* bi     = (const float*)d_in[5];
    const float* Wh     = (const float*)d_in[6];
    const float* bh     = (const float*)d_in[7];
    float* out = (float*)d_out;

    cudaFuncSetAttribute(gru_mma_kernel,
                         cudaFuncAttributeMaxDynamicSharedMemorySize, SMEM_BYTES);
    // grid.x = 8 n-slices (fast dim -> concurrent CTAs share X in L2),
    // grid.y = 128 batch tiles of 128 rows
    gru_mma_kernel<<<dim3(8, 128), 512, SMEM_BYTES>>>(
        input, hidden, Wg, bg, Wi, bi, Wh, bh, out);
}

// round 8
// speedup vs baseline: 1.2549x; 1.0411x over previous
#include <cuda_runtime.h>
#include <cstdint>
#include <cstddef>

// ---------------------------------------------------------------------------
// Fused GRU cell via mma.sync tf32 (compute_103-safe PTX; no tcgen05/TMA).
// R8: fill cp.asyncs spread inside the ks loop (off the post-barrier critical
// path), A-fragment double-buffer prefetch, B loaded at ks top under the
// previous ks's MMA issue tail. BK=64, 512-thr CTA, M=128 x 64 units,
// pitch-256 rows with per-128B-half SW128; LDSM addr = base ^ (ks<<5).
//
// B operand rows (192), per wn slice s = wn*48:
//   rows [s+ 0,s+16): W_gate[n0+wn*16+u]     -> r (nb 0,1)
//   rows [s+16,s+32): W_gate[512+n0+wn*16+u] -> z (nb 2,3)
//   rows [s+32,s+48): Wi/Wh[n0+wn*16+u]      -> i/h (nb 4,5, phase split)
// kt<8: X=input, ih=Wi -> alo. kt>=8: X=hidden, ih=Wh -> ahi.
// ---------------------------------------------------------------------------

__device__ __forceinline__ uint32_t smem_u32(const void* p) {
    uint32_t a;
    asm("{ .reg .u64 t; cvta.to.shared.u64 t, %1; cvt.u32.u64 %0, t; }"
        : "=r"(a) : "l"(p));
    return a;
}

__device__ __forceinline__ void cp16(uint32_t dst, const float* src) {
    asm volatile("cp.async.cg.shared.global [%0], [%1], 16;"
                 :: "r"(dst), "l"(src) : "memory");
}
#define CP_COMMIT() asm volatile("cp.async.commit_group;" ::: "memory")
#define CP_WAIT0()  asm volatile("cp.async.wait_group 0;" ::: "memory")

__device__ __forceinline__ void ldsm4(uint32_t& r0, uint32_t& r1,
                                      uint32_t& r2, uint32_t& r3, uint32_t addr) {
    asm volatile("ldmatrix.sync.aligned.m8n8.x4.shared.b16 {%0,%1,%2,%3}, [%4];"
                 : "=r"(r0), "=r"(r1), "=r"(r2), "=r"(r3) : "r"(addr));
}

__device__ __forceinline__ void mma8(float* c, const uint32_t* a,
                                     uint32_t b0, uint32_t b1) {
    asm volatile(
        "mma.sync.aligned.m16n8k8.row.col.f32.tf32.tf32.f32 "
        "{%0,%1,%2,%3}, {%4,%5,%6,%7}, {%8,%9}, {%0,%1,%2,%3};"
        : "+f"(c[0]), "+f"(c[1]), "+f"(c[2]), "+f"(c[3])
        : "r"(a[0]), "r"(a[1]), "r"(a[2]), "r"(a[3]), "r"(b0), "r"(b1));
}

__device__ __forceinline__ float fsigmoid(float x) {
    return 1.0f / (1.0f + __expf(-x));
}
__device__ __forceinline__ float ftanh(float x) {
    float e = __expf(2.0f * x);          // overflow->inf, underflow->0: safe
    return 1.0f - 2.0f / (e + 1.0f);
}

// ---- geometry ----
// Rows are 256B (64 tf32). Physical offset of (row, col byte c):
//   row*256 + (c>>7)*128 + ((c&127) ^ ((row&7)<<4))   [SW128 per 128B half]
static constexpr int A_BYTES     = 128 * 256;          // 32KB
static constexpr int B_BYTES     = 192 * 256;          // 48KB
static constexpr int STAGE_BYTES = A_BYTES + B_BYTES;  // 81920
static constexpr int SMEM_BYTES  = 1024 + 1024 + 2 * STAGE_BYTES;  // ~162KB

__device__ __forceinline__ uint32_t fill_off(int u) {
    const int r = u >> 4, cu = u & 15;
    return (uint32_t)(r * 256 + ((cu >> 3) << 7) + (((cu & 7) * 16) ^ ((r & 7) << 4)));
}

// Compute one BK=64 tile; optionally interleave the next stage's fill.
template <bool PH, bool FILL>
__device__ __forceinline__ void compute_tile(
    uint32_t stg, uint32_t fstg, uint32_t aoff0, uint32_t boff0,
    uint32_t fA0, uint32_t fB0,
    const float*& pA0, const float* (&pB)[6],
    float (&alo)[2][6][4], float (&ahi)[2][2][4])
{
    uint32_t a[2][2][4];   // A double buffer [buf][mi][reg]
    uint32_t b[6][2];      // B single buffer

    // ks=0 fragments first: post-barrier critical path is LDSM->MMA.
    #pragma unroll
    for (int mi = 0; mi < 2; mi++)
        ldsm4(a[0][mi][0], a[0][mi][1], a[0][mi][2], a[0][mi][3],
              stg + aoff0 + mi * 4096);
    #pragma unroll
    for (int p = 0; p < 3; p++)
        ldsm4(b[2 * p][0], b[2 * p][1], b[2 * p + 1][0], b[2 * p + 1][1],
              stg + boff0 + p * 4096);

    #pragma unroll
    for (int ks = 0; ks < 8; ks++) {
        const int cur = ks & 1, nxt = cur ^ 1;
        // Prefetch A(ks+1) under this ks's MMAs.
        if (ks < 7) {
            const uint32_t kx = (uint32_t)((ks + 1) << 5);
            #pragma unroll
            for (int mi = 0; mi < 2; mi++)
                ldsm4(a[nxt][mi][0], a[nxt][mi][1], a[nxt][mi][2], a[nxt][mi][3],
                      stg + (aoff0 ^ kx) + mi * 4096);
        }
        // Spread the next-stage fill across early ks steps.
        if (FILL) {
            if (ks == 0) {
                #pragma unroll
                for (int i = 0; i < 4; i++)
                    cp16(fstg + fA0 + (uint32_t)i * 8192u, pA0 + i * 16384);
            } else if (ks < 4) {
                const int i0 = 2 * (ks - 1);
                cp16(fstg + fB0 + (uint32_t)i0 * 8192u, pB[i0]);
                cp16(fstg + fB0 + (uint32_t)(i0 + 1) * 8192u, pB[i0 + 1]);
                if (ks == 3) CP_COMMIT();
            }
        }
        // 12 MMAs for this ks (b is free to be overwritten once issued).
        #pragma unroll
        for (int mi = 0; mi < 2; mi++) {
            #pragma unroll
            for (int nb = 0; nb < 6; nb++) {
                if (PH && nb >= 4)
                    mma8(ahi[mi][nb - 4], a[cur][mi], b[nb][0], b[nb][1]);
                else
                    mma8(alo[mi][nb], a[cur][mi], b[nb][0], b[nb][1]);
            }
        }
        // Load B(ks+1) after its consumers issued; ~30cyc latency hides
        // under the 12-MMA issue tail and other warps.
        if (ks < 7) {
            const uint32_t kx = (uint32_t)((ks + 1) << 5);
            #pragma unroll
            for (int p = 0; p < 3; p++)
                ldsm4(b[2 * p][0], b[2 * p][1], b[2 * p + 1][0], b[2 * p + 1][1],
                      stg + (boff0 ^ kx) + p * 4096);
        }
    }
    if (FILL) {
        pA0 += 64;
        #pragma unroll
        for (int i = 0; i < 6; i++) pB[i] += 64;
    }
}

__global__ void __launch_bounds__(512, 1)
gru_mma_kernel(const float* __restrict__ input, const float* __restrict__ hidden,
               const float* __restrict__ Wg, const float* __restrict__ bg,
               const float* __restrict__ Wi, const float* __restrict__ bi,
               const float* __restrict__ Wh, const float* __restrict__ bh,
               float* __restrict__ out)
{
    extern __shared__ char dsm[];
    const int tid  = threadIdx.x;
    const int lane = tid & 31;
    const int wid  = tid >> 5;
    const int wm   = wid >> 2;          // 0..3 (M, 32 rows each)
    const int wn   = wid & 3;           // 0..3 (N slice, 16 units each)
    const int n0 = blockIdx.x * 64;     // hidden-unit slice
    const int m0 = blockIdx.y * 128;    // batch-row slice

    const uint32_t raw = smem_u32(dsm);
    const uint32_t sb  = (raw + 1023u) & ~1023u;
    char* gb = dsm + (sb - raw);
    const uint32_t stage0 = sb + 1024;
    const uint32_t stage1 = stage0 + STAGE_BYTES;

    // biases: br[64]@0, bz@64, bi@128, bh@192 (floats)
    float* sbias = (float*)gb;
    if (tid < 256) {
        int g = tid >> 6, j = tid & 63;
        float v;
        if (g == 0)      v = bg[n0 + j];
        else if (g == 1) v = bg[512 + n0 + j];
        else if (g == 2) v = bi[n0 + j];
        else             v = bh[n0 + j];
        sbias[tid] = v;
    }

    // ---- fill state ----
    const uint32_t fA0 = fill_off(tid);                        // + i*8192
    const uint32_t fB0 = (uint32_t)A_BYTES + fill_off(tid);    // + i*8192
    const int frow = tid >> 4, fcu = (tid & 15) * 4;
    const float* pA0 = input + (m0 + frow) * 512 + fcu;        // + i*16384
    const float* pB[6];
    bool isw[6];
    #pragma unroll
    for (int i = 0; i < 6; i++) {
        const int r = frow + 32 * i;
        const int ws = r / 48, rr = r - ws * 48;
        const int un = n0 + ws * 16;
        isw[i] = (rr >= 32);
        if (rr < 16)       pB[i] = Wg + (un + rr) * 1024 + fcu;
        else if (rr < 32)  pB[i] = Wg + (512 + un + rr - 16) * 1024 + fcu;
        else               pB[i] = Wi + (un + rr - 32) * 512 + fcu;
    }
    const ptrdiff_t dxa = (hidden - input) - 512;
    const ptrdiff_t dwh = (Wh - Wi) - 512;

    // ---- LDSM base offsets ----
    uint32_t aoff0, boff0;
    {
        const uint32_t arow = (uint32_t)(wm * 32 + (lane & 7) + ((lane >> 3) & 1) * 8);
        const uint32_t acb  = (uint32_t)((lane >> 4) * 16);
        const uint32_t brow = (uint32_t)(wn * 48 + ((lane >> 4) * 8) + (lane & 7));
        const uint32_t bcb  = (uint32_t)(((lane >> 3) & 1) * 16);
        aoff0 = arow * 256 + (acb ^ ((arow & 7) << 4));                     // + mi*4096
        boff0 = (uint32_t)A_BYTES + brow * 256 + (bcb ^ ((brow & 7) << 4)); // + p*4096
    }

    float alo[2][6][4];
    float ahi[2][2][4];
    #pragma unroll
    for (int mi = 0; mi < 2; mi++) {
        #pragma unroll
        for (int nb = 0; nb < 6; nb++)
            #pragma unroll
            for (int e = 0; e < 4; e++) alo[mi][nb][e] = 0.0f;
        #pragma unroll
        for (int nb = 0; nb < 2; nb++)
            #pragma unroll
            for (int e = 0; e < 4; e++) ahi[mi][nb][e] = 0.0f;
    }

    // prologue: fill stage0 for kt=0 (bunched; one-time cost)
    {
        #pragma unroll
        for (int i = 0; i < 4; i++)
            cp16(stage0 + fA0 + (uint32_t)i * 8192u, pA0 + i * 16384);
        pA0 += 64;
        #pragma unroll
        for (int i = 0; i < 6; i++) {
            cp16(stage0 + fB0 + (uint32_t)i * 8192u, pB[i]);
            pB[i] += 64;
        }
        CP_COMMIT();
    }

    // Phase 0: kt = 0..7 (X=input, ih=Wi -> alo). Fill(kt+1) happens inside
    // compute_tile, spread over ks=0..3; barrier protects the WAR on the
    // stage being refilled.
    #pragma unroll 2
    for (int kt = 0; kt < 8; kt++) {
        const uint32_t stg  = (kt & 1) ? stage1 : stage0;
        const uint32_t fstg = (kt & 1) ? stage0 : stage1;
        CP_WAIT0();
        __syncthreads();
        if (kt == 7) {   // next fill f=8: switch xa->hidden, Wi->Wh
            pA0 += dxa;
            #pragma unroll
            for (int i = 0; i < 6; i++) if (isw[i]) pB[i] += dwh;
        }
        compute_tile<false, true>(stg, fstg, aoff0, boff0, fA0, fB0,
                                  pA0, pB, alo, ahi);
    }
    // Phase 1: kt = 8..15 (X=hidden, ih=Wh -> ahi); last iter fills nothing.
    #pragma unroll 2
    for (int kt = 8; kt < 15; kt++) {
        const uint32_t stg  = (kt & 1) ? stage1 : stage0;
        const uint32_t fstg = (kt & 1) ? stage0 : stage1;
        CP_WAIT0();
        __syncthreads();
        compute_tile<true, true>(stg, fstg, aoff0, boff0, fA0, fB0,
                                 pA0, pB, alo, ahi);
    }
    {
        CP_WAIT0();
        __syncthreads();
        compute_tile<true, false>(stage1, stage0, aoff0, boff0, fA0, fB0,
                                  pA0, pB, alo, ahi);
    }

    // ---- register-resident epilogue ----
    const float* sb_r = sbias;
    const float* sb_z = sbias + 64;
    const float* sb_i = sbias + 128;
    const float* sb_h = sbias + 192;

    #pragma unroll
    for (int mi = 0; mi < 2; mi++) {
        #pragma unroll
        for (int unb = 0; unb < 2; unb++) {
            const int uu = wn * 16 + unb * 8 + 2 * (lane & 3);   // unit (local)
            const float br0 = sb_r[uu], br1 = sb_r[uu + 1];
            const float bz0 = sb_z[uu], bz1 = sb_z[uu + 1];
            const float bi0 = sb_i[uu], bi1 = sb_i[uu + 1];
            const float bh0 = sb_h[uu], bh1 = sb_h[uu + 1];
            #pragma unroll
            for (int half = 0; half < 2; half++) {
                const int m = wm * 32 + mi * 16 + (lane >> 2) + 8 * half;
                const float rv0 = fsigmoid(alo[mi][0 + unb][2 * half]     + br0);
                const float rv1 = fsigmoid(alo[mi][0 + unb][2 * half + 1] + br1);
                const float zv0 = fsigmoid(alo[mi][2 + unb][2 * half]     + bz0);
                const float zv1 = fsigmoid(alo[mi][2 + unb][2 * half + 1] + bz1);
                const float iv0 = alo[mi][4 + unb][2 * half];
                const float iv1 = alo[mi][4 + unb][2 * half + 1];
                const float hv0 = ahi[mi][unb][2 * half];
                const float hv1 = ahi[mi][unb][2 * half + 1];
                const float2 hg = *(const float2*)&hidden[(m0 + m) * 512 + n0 + uu];
                const float ng0 = ftanh(iv0 + bi0 + rv0 * (hv0 + bh0));
                const float ng1 = ftanh(iv1 + bi1 + rv1 * (hv1 + bh1));
                float2 o;
                o.x = (1.0f - zv0) * ng0 + zv0 * hg.x;
                o.y = (1.0f - zv1) * ng1 + zv1 * hg.y;
                *(float2*)&out[(m0 + m) * 512 + n0 + uu] = o;
            }
        }
    }
}

extern "C" void kernel_launch(void* const* d_in, const int* in_sizes, int n_in,
                              void* d_out, int out_size)
{
    const float* input  = (const float*)d_in[0];
    const float* hidden = (const float*)d_in[1];
    const float* Wg     = (const float*)d_in[2];
    const float* bg     = (const float*)d_in[3];
    const float* Wi     = (const float*)d_in[4];
    const float* bi     = (const float*)d_in[5];
    const float* Wh     = (const float*)d_in[6];
    const float* bh     = (const float*)d_in[7];
    float* out = (float*)d_out;

    cudaFuncSetAttribute(gru_mma_kernel,
                         cudaFuncAttributeMaxDynamicSharedMemorySize, SMEM_BYTES);
    gru_mma_kernel<<<dim3(8, 128), 512, SMEM_BYTES>>>(
        input, hidden, Wg, bg, Wi, bi, Wh, bh, out);
}

// round 9
// speedup vs baseline: 1.7244x; 1.3741x over previous
#include <cuda_runtime.h>
#include <cuda_fp16.h>
#include <cstdint>
#include <cstddef>

// ---------------------------------------------------------------------------
// Fused GRU cell, fp16 tensor-core path (compute_103-safe PTX).
// R9: tf32 -> fp16 m16n8k16. Same 11-bit mantissa as tf32 (rel_err preserved),
// 2x tensor rate, half the smem/L2/DRAM bytes. A pre-pass converts the five
// fp32 operand arrays to fp16 in __device__ scratch; the GEMM kernel is the
// R8 structure with BK=128 (8 k-iters), identical byte-level ldmatrix
// addressing (verified: fp16 m16n8k16 A/B fragments map onto the same
// m8n8.b16 tile addresses and the same  addr = base ^ (ks<<5)  swizzle).
//
// B operand rows (192), per wn slice s = wn*48:
//   rows [s+ 0,s+16): W_gate[n0+wn*16+u]     -> r (nb 0,1)
//   rows [s+16,s+32): W_gate[512+n0+wn*16+u] -> z (nb 2,3)
//   rows [s+32,s+48): Wi/Wh[n0+wn*16+u]      -> i/h (nb 4,5, phase split)
// kt<4: X=input, ih=Wi -> alo. kt>=4: X=hidden, ih=Wh -> ahi.
// Epilogue uses ORIGINAL fp32 hidden for the z*h term.
// ---------------------------------------------------------------------------

// ---- fp16 scratch (device global: allocation-free) ----
static constexpr size_t OFF_IN  = 0;                        // 16384x512
static constexpr size_t OFF_HID = 8388608;                  // 16384x512
static constexpr size_t OFF_WG  = 16777216;                 // 1024x1024
static constexpr size_t OFF_WI  = 17825792;                 // 512x512
static constexpr size_t OFF_WH  = 18087936;                 // 512x512
static constexpr size_t CVT_TOTAL = 18350080;               // 35MB
__device__ __half g_cvt[CVT_TOTAL];

__global__ void cvt_kernel(const float4* __restrict__ src, size_t dst_off, int n4) {
    const int i = blockIdx.x * blockDim.x + threadIdx.x;
    if (i < n4) {
        const float4 v = src[i];
        __half2* dst = reinterpret_cast<__half2*>(g_cvt + dst_off);
        dst[2 * i]     = __floats2half2_rn(v.x, v.y);
        dst[2 * i + 1] = __floats2half2_rn(v.z, v.w);
    }
}

// ---- helpers ----
__device__ __forceinline__ uint32_t smem_u32(const void* p) {
    uint32_t a;
    asm("{ .reg .u64 t; cvta.to.shared.u64 t, %1; cvt.u32.u64 %0, t; }"
        : "=r"(a) : "l"(p));
    return a;
}

__device__ __forceinline__ void cp16(uint32_t dst, const __half* src) {
    asm volatile("cp.async.cg.shared.global [%0], [%1], 16;"
                 :: "r"(dst), "l"(src) : "memory");
}
#define CP_COMMIT() asm volatile("cp.async.commit_group;" ::: "memory")
#define CP_WAIT0()  asm volatile("cp.async.wait_group 0;" ::: "memory")

__device__ __forceinline__ void ldsm4(uint32_t& r0, uint32_t& r1,
                                      uint32_t& r2, uint32_t& r3, uint32_t addr) {
    asm volatile("ldmatrix.sync.aligned.m8n8.x4.shared.b16 {%0,%1,%2,%3}, [%4];"
                 : "=r"(r0), "=r"(r1), "=r"(r2), "=r"(r3) : "r"(addr));
}

__device__ __forceinline__ void mma16(float* c, const uint32_t* a,
                                      uint32_t b0, uint32_t b1) {
    asm volatile(
        "mma.sync.aligned.m16n8k16.row.col.f32.f16.f16.f32 "
        "{%0,%1,%2,%3}, {%4,%5,%6,%7}, {%8,%9}, {%0,%1,%2,%3};"
        : "+f"(c[0]), "+f"(c[1]), "+f"(c[2]), "+f"(c[3])
        : "r"(a[0]), "r"(a[1]), "r"(a[2]), "r"(a[3]), "r"(b0), "r"(b1));
}

__device__ __forceinline__ float fsigmoid(float x) {
    return 1.0f / (1.0f + __expf(-x));
}
__device__ __forceinline__ float ftanh(float x) {
    float e = __expf(2.0f * x);          // overflow->inf, underflow->0: safe
    return 1.0f - 2.0f / (e + 1.0f);
}

// ---- geometry ----
// Rows are 256B (128 fp16). Physical offset of (row, col byte c):
//   row*256 + (c>>7)*128 + ((c&127) ^ ((row&7)<<4))   [SW128 per 128B half]
static constexpr int A_BYTES     = 128 * 256;          // 32KB: 128 rows x 128 fp16
static constexpr int B_BYTES     = 192 * 256;          // 48KB
static constexpr int STAGE_BYTES = A_BYTES + B_BYTES;  // 81920
static constexpr int SMEM_BYTES  = 1024 + 1024 + 2 * STAGE_BYTES;  // ~162KB

__device__ __forceinline__ uint32_t fill_off(int u) {
    const int r = u >> 4, cu = u & 15;
    return (uint32_t)(r * 256 + ((cu >> 3) << 7) + (((cu & 7) * 16) ^ ((r & 7) << 4)));
}

// Compute one BK=128 tile (8 x k16); optionally interleave next-stage fill.
template <bool PH, bool FILL>
__device__ __forceinline__ void compute_tile(
    uint32_t stg, uint32_t fstg, uint32_t aoff0, uint32_t boff0,
    uint32_t fA0, uint32_t fB0,
    const __half*& pA0, const __half* (&pB)[6],
    float (&alo)[2][6][4], float (&ahi)[2][2][4])
{
    uint32_t a[2][2][4];   // A double buffer [buf][mi][reg]
    uint32_t b[6][2];      // B single buffer

    #pragma unroll
    for (int mi = 0; mi < 2; mi++)
        ldsm4(a[0][mi][0], a[0][mi][1], a[0][mi][2], a[0][mi][3],
              stg + aoff0 + mi * 4096);
    #pragma unroll
    for (int p = 0; p < 3; p++)
        ldsm4(b[2 * p][0], b[2 * p][1], b[2 * p + 1][0], b[2 * p + 1][1],
              stg + boff0 + p * 4096);

    #pragma unroll
    for (int ks = 0; ks < 8; ks++) {
        const int cur = ks & 1, nxt = cur ^ 1;
        if (ks < 7) {
            const uint32_t kx = (uint32_t)((ks + 1) << 5);
            #pragma unroll
            for (int mi = 0; mi < 2; mi++)
                ldsm4(a[nxt][mi][0], a[nxt][mi][1], a[nxt][mi][2], a[nxt][mi][3],
                      stg + (aoff0 ^ kx) + mi * 4096);
        }
        if (FILL) {
            if (ks == 0) {
                #pragma unroll
                for (int i = 0; i < 4; i++)
                    cp16(fstg + fA0 + (uint32_t)i * 8192u, pA0 + i * 16384);
            } else if (ks < 4) {
                const int i0 = 2 * (ks - 1);
                cp16(fstg + fB0 + (uint32_t)i0 * 8192u, pB[i0]);
                cp16(fstg + fB0 + (uint32_t)(i0 + 1) * 8192u, pB[i0 + 1]);
                if (ks == 3) CP_COMMIT();
            }
        }
        #pragma unroll
        for (int mi = 0; mi < 2; mi++) {
            #pragma unroll
            for (int nb = 0; nb < 6; nb++) {
                if (PH && nb >= 4)
                    mma16(ahi[mi][nb - 4], a[cur][mi], b[nb][0], b[nb][1]);
                else
                    mma16(alo[mi][nb], a[cur][mi], b[nb][0], b[nb][1]);
            }
        }
        if (ks < 7) {
            const uint32_t kx = (uint32_t)((ks + 1) << 5);
            #pragma unroll
            for (int p = 0; p < 3; p++)
                ldsm4(b[2 * p][0], b[2 * p][1], b[2 * p + 1][0], b[2 * p + 1][1],
                      stg + (boff0 ^ kx) + p * 4096);
        }
    }
    if (FILL) {
        pA0 += 128;
        #pragma unroll
        for (int i = 0; i < 6; i++) pB[i] += 128;
    }
}

__global__ void __launch_bounds__(512, 1)
gru_mma_kernel(const float* __restrict__ hidden, const float* __restrict__ bg,
               const float* __restrict__ bi, const float* __restrict__ bh,
               float* __restrict__ out)
{
    extern __shared__ char dsm[];
    const int tid  = threadIdx.x;
    const int lane = tid & 31;
    const int wid  = tid >> 5;
    const int wm   = wid >> 2;          // 0..3 (M, 32 rows each)
    const int wn   = wid & 3;           // 0..3 (N slice, 16 units each)
    const int n0 = blockIdx.x * 64;     // hidden-unit slice
    const int m0 = blockIdx.y * 128;    // batch-row slice

    const __half* cIn  = g_cvt + OFF_IN;
    const __half* cHid = g_cvt + OFF_HID;
    const __half* cWg  = g_cvt + OFF_WG;
    const __half* cWi  = g_cvt + OFF_WI;
    const __half* cWh  = g_cvt + OFF_WH;

    const uint32_t raw = smem_u32(dsm);
    const uint32_t sb  = (raw + 1023u) & ~1023u;
    char* gb = dsm + (sb - raw);
    const uint32_t stage0 = sb + 1024;
    const uint32_t stage1 = stage0 + STAGE_BYTES;

    // biases: br[64]@0, bz@64, bi@128, bh@192 (floats)
    float* sbias = (float*)gb;
    if (tid < 256) {
        int g = tid >> 6, j = tid & 63;
        float v;
        if (g == 0)      v = bg[n0 + j];
        else if (g == 1) v = bg[512 + n0 + j];
        else if (g == 2) v = bi[n0 + j];
        else             v = bh[n0 + j];
        sbias[tid] = v;
    }

    // ---- fill state (16B chunk = 8 halfs) ----
    const uint32_t fA0 = fill_off(tid);                        // + i*8192
    const uint32_t fB0 = (uint32_t)A_BYTES + fill_off(tid);    // + i*8192
    const int frow = tid >> 4, fcu = (tid & 15) * 8;
    const __half* pA0 = cIn + (m0 + frow) * 512 + fcu;         // + i*16384 halfs
    const __half* pB[6];
    bool isw[6];
    #pragma unroll
    for (int i = 0; i < 6; i++) {
        const int r = frow + 32 * i;
        const int ws = r / 48, rr = r - ws * 48;
        const int un = n0 + ws * 16;
        isw[i] = (rr >= 32);
        if (rr < 16)       pB[i] = cWg + (un + rr) * 1024 + fcu;
        else if (rr < 32)  pB[i] = cWg + (512 + un + rr - 16) * 1024 + fcu;
        else               pB[i] = cWi + (un + rr - 32) * 512 + fcu;
    }
    // Phase switch (after 4 fills of +128): xa = in+row*512+512 -> hid+row*512.
    const ptrdiff_t dxa = (cHid - cIn) - 512;
    const ptrdiff_t dwh = (cWh - cWi) - 512;

    // ---- LDSM base offsets (identical byte math to the tf32 version) ----
    uint32_t aoff0, boff0;
    {
        const uint32_t arow = (uint32_t)(wm * 32 + (lane & 7) + ((lane >> 3) & 1) * 8);
        const uint32_t acb  = (uint32_t)((lane >> 4) * 16);
        const uint32_t brow = (uint32_t)(wn * 48 + ((lane >> 4) * 8) + (lane & 7));
        const uint32_t bcb  = (uint32_t)(((lane >> 3) & 1) * 16);
        aoff0 = arow * 256 + (acb ^ ((arow & 7) << 4));                     // + mi*4096
        boff0 = (uint32_t)A_BYTES + brow * 256 + (bcb ^ ((brow & 7) << 4)); // + p*4096
    }

    float alo[2][6][4];
    float ahi[2][2][4];
    #pragma unroll
    for (int mi = 0; mi < 2; mi++) {
        #pragma unroll
        for (int nb = 0; nb < 6; nb++)
            #pragma unroll
            for (int e = 0; e < 4; e++) alo[mi][nb][e] = 0.0f;
        #pragma unroll
        for (int nb = 0; nb < 2; nb++)
            #pragma unroll
            for (int e = 0; e < 4; e++) ahi[mi][nb][e] = 0.0f;
    }

    // prologue: fill stage0 for kt=0
    {
        #pragma unroll
        for (int i = 0; i < 4; i++)
            cp16(stage0 + fA0 + (uint32_t)i * 8192u, pA0 + i * 16384);
        pA0 += 128;
        #pragma unroll
        for (int i = 0; i < 6; i++) {
            cp16(stage0 + fB0 + (uint32_t)i * 8192u, pB[i]);
            pB[i] += 128;
        }
        CP_COMMIT();
    }

    // Phase 0: kt = 0..3 (X=input, ih=Wi -> alo)
    #pragma unroll 2
    for (int kt = 0; kt < 4; kt++) {
        const uint32_t stg  = (kt & 1) ? stage1 : stage0;
        const uint32_t fstg = (kt & 1) ? stage0 : stage1;
        CP_WAIT0();
        __syncthreads();
        if (kt == 3) {   // next fill f=4: switch xa->hidden, Wi->Wh
            pA0 += dxa;
            #pragma unroll
            for (int i = 0; i < 6; i++) if (isw[i]) pB[i] += dwh;
        }
        compute_tile<false, true>(stg, fstg, aoff0, boff0, fA0, fB0,
                                  pA0, pB, alo, ahi);
    }
    // Phase 1: kt = 4..7 (X=hidden, ih=Wh -> ahi); last iter fills nothing.
    #pragma unroll 2
    for (int kt = 4; kt < 7; kt++) {
        const uint32_t stg  = (kt & 1) ? stage1 : stage0;
        const uint32_t fstg = (kt & 1) ? stage0 : stage1;
        CP_WAIT0();
        __syncthreads();
        compute_tile<true, true>(stg, fstg, aoff0, boff0, fA0, fB0,
                                 pA0, pB, alo, ahi);
    }
    {
        CP_WAIT0();
        __syncthreads();
        compute_tile<true, false>(stage1, stage0, aoff0, boff0, fA0, fB0,
                                  pA0, pB, alo, ahi);
    }

    // ---- register-resident epilogue (fp32 hidden for the z*h term) ----
    const float* sb_r = sbias;
    const float* sb_z = sbias + 64;
    const float* sb_i = sbias + 128;
    const float* sb_h = sbias + 192;

    #pragma unroll
    for (int mi = 0; mi < 2; mi++) {
        #pragma unroll
        for (int unb = 0; unb < 2; unb++) {
            const int uu = wn * 16 + unb * 8 + 2 * (lane & 3);   // unit (local)
            const float br0 = sb_r[uu], br1 = sb_r[uu + 1];
            const float bz0 = sb_z[uu], bz1 = sb_z[uu + 1];
            const float bi0 = sb_i[uu], bi1 = sb_i[uu + 1];
            const float bh0 = sb_h[uu], bh1 = sb_h[uu + 1];
            #pragma unroll
            for (int half = 0; half < 2; half++) {
                const int m = wm * 32 + mi * 16 + (lane >> 2) + 8 * half;
                const float rv0 = fsigmoid(alo[mi][0 + unb][2 * half]     + br0);
                const float rv1 = fsigmoid(alo[mi][0 + unb][2 * half + 1] + br1);
                const float zv0 = fsigmoid(alo[mi][2 + unb][2 * half]     + bz0);
                const float zv1 = fsigmoid(alo[mi][2 + unb][2 * half + 1] + bz1);
                const float iv0 = alo[mi][4 + unb][2 * half];
                const float iv1 = alo[mi][4 + unb][2 * half + 1];
                const float hv0 = ahi[mi][unb][2 * half];
                const float hv1 = ahi[mi][unb][2 * half + 1];
                const float2 hg = *(const float2*)&hidden[(m0 + m) * 512 + n0 + uu];
                const float ng0 = ftanh(iv0 + bi0 + rv0 * (hv0 + bh0));
                const float ng1 = ftanh(iv1 + bi1 + rv1 * (hv1 + bh1));
                float2 o;
                o.x = (1.0f - zv0) * ng0 + zv0 * hg.x;
                o.y = (1.0f - zv1) * ng1 + zv1 * hg.y;
                *(float2*)&out[(m0 + m) * 512 + n0 + uu] = o;
            }
        }
    }
}

extern "C" void kernel_launch(void* const* d_in, const int* in_sizes, int n_in,
                              void* d_out, int out_size)
{
    const float* input  = (const float*)d_in[0];
    const float* hidden = (const float*)d_in[1];
    const float* Wg     = (const float*)d_in[2];
    const float* bg     = (const float*)d_in[3];
    const float* Wi     = (const float*)d_in[4];
    const float* bi     = (const float*)d_in[5];
    const float* Wh     = (const float*)d_in[6];
    const float* bh     = (const float*)d_in[7];
    float* out = (float*)d_out;

    // fp32 -> fp16 conversion pre-pass (all graph-capturable kernel launches)
    cvt_kernel<<<(2097152 + 255) / 256, 256>>>((const float4*)input,  OFF_IN,  2097152);
    cvt_kernel<<<(2097152 + 255) / 256, 256>>>((const float4*)hidden, OFF_HID, 2097152);
    cvt_kernel<<<(262144  + 255) / 256, 256>>>((const float4*)Wg,     OFF_WG,  262144);
    cvt_kernel<<<(65536   + 255) / 256, 256>>>((const float4*)Wi,     OFF_WI,  65536);
    cvt_kernel<<<(65536   + 255) / 256, 256>>>((const float4*)Wh,     OFF_WH,  65536);

    cudaFuncSetAttribute(gru_mma_kernel,
                         cudaFuncAttributeMaxDynamicSharedMemorySize, SMEM_BYTES);
    gru_mma_kernel<<<dim3(8, 128), 512, SMEM_BYTES>>>(hidden, bg, bi, bh, out);
}

// round 10
// speedup vs baseline: 1.9679x; 1.1412x over previous
#include <cuda_runtime.h>
#include <cuda_fp16.h>
#include <cstdint>
#include <cstddef>

// ---------------------------------------------------------------------------
// Fused GRU cell, fp16 tensor-core path (compute_103-safe PTX).
// R10: 256-thread CTAs, tile M=128 x 32 units, BK=128, 2 CTAs/SM so barrier
// drain of one CTA overlaps with the other CTA's MMAs. Biases moved out of
// smem (direct global loads in the epilogue) to fit 2 x 114816B under the
// 228KB smem limit. Warp layout 4(M) x 2(N); warp tile unchanged from R9.
//
// B operand rows (96), per wn slice s = wn*48:
//   rows [s+ 0,s+16): W_gate[n0+wn*16+u]     -> r (nb 0,1)
//   rows [s+16,s+32): W_gate[512+n0+wn*16+u] -> z (nb 2,3)
//   rows [s+32,s+48): Wi/Wh[n0+wn*16+u]      -> i/h (nb 4,5, phase split)
// kt<4: X=input, ih=Wi -> alo. kt>=4: X=hidden, ih=Wh -> ahi.
// Epilogue uses ORIGINAL fp32 hidden for the z*h term.
// ---------------------------------------------------------------------------

// ---- fp16 scratch (device global: allocation-free) ----
static constexpr size_t OFF_IN  = 0;                        // 16384x512
static constexpr size_t OFF_HID = 8388608;                  // 16384x512
static constexpr size_t OFF_WG  = 16777216;                 // 1024x1024
static constexpr size_t OFF_WI  = 17825792;                 // 512x512
static constexpr size_t OFF_WH  = 18087936;                 // 512x512
static constexpr size_t CVT_TOTAL = 18350080;               // 35MB
__device__ __half g_cvt[CVT_TOTAL];

__global__ void cvt_kernel(const float4* __restrict__ src, size_t dst_off, int n4) {
    const int i = blockIdx.x * blockDim.x + threadIdx.x;
    if (i < n4) {
        const float4 v = src[i];
        __half2* dst = reinterpret_cast<__half2*>(g_cvt + dst_off);
        dst[2 * i]     = __floats2half2_rn(v.x, v.y);
        dst[2 * i + 1] = __floats2half2_rn(v.z, v.w);
    }
}

// ---- helpers ----
__device__ __forceinline__ uint32_t smem_u32(const void* p) {
    uint32_t a;
    asm("{ .reg .u64 t; cvta.to.shared.u64 t, %1; cvt.u32.u64 %0, t; }"
        : "=r"(a) : "l"(p));
    return a;
}

__device__ __forceinline__ void cp16(uint32_t dst, const __half* src) {
    asm volatile("cp.async.cg.shared.global [%0], [%1], 16;"
                 :: "r"(dst), "l"(src) : "memory");
}
#define CP_COMMIT() asm volatile("cp.async.commit_group;" ::: "memory")
#define CP_WAIT0()  asm volatile("cp.async.wait_group 0;" ::: "memory")

__device__ __forceinline__ void ldsm4(uint32_t& r0, uint32_t& r1,
                                      uint32_t& r2, uint32_t& r3, uint32_t addr) {
    asm volatile("ldmatrix.sync.aligned.m8n8.x4.shared.b16 {%0,%1,%2,%3}, [%4];"
                 : "=r"(r0), "=r"(r1), "=r"(r2), "=r"(r3) : "r"(addr));
}

__device__ __forceinline__ void mma16(float* c, const uint32_t* a,
                                      uint32_t b0, uint32_t b1) {
    asm volatile(
        "mma.sync.aligned.m16n8k16.row.col.f32.f16.f16.f32 "
        "{%0,%1,%2,%3}, {%4,%5,%6,%7}, {%8,%9}, {%0,%1,%2,%3};"
        : "+f"(c[0]), "+f"(c[1]), "+f"(c[2]), "+f"(c[3])
        : "r"(a[0]), "r"(a[1]), "r"(a[2]), "r"(a[3]), "r"(b0), "r"(b1));
}

__device__ __forceinline__ float fsigmoid(float x) {
    return 1.0f / (1.0f + __expf(-x));
}
__device__ __forceinline__ float ftanh(float x) {
    float e = __expf(2.0f * x);          // overflow->inf, underflow->0: safe
    return 1.0f - 2.0f / (e + 1.0f);
}

// ---- geometry ----
// Rows are 256B (128 fp16). Physical offset of (row, col byte c):
//   row*256 + (c>>7)*128 + ((c&127) ^ ((row&7)<<4))   [SW128 per 128B half]
static constexpr int A_BYTES     = 128 * 256;          // 32KB
static constexpr int B_BYTES     = 96 * 256;           // 24KB
static constexpr int STAGE_BYTES = A_BYTES + B_BYTES;  // 57344
static constexpr int SMEM_BYTES  = 128 + 2 * STAGE_BYTES;  // 114816/CTA

__device__ __forceinline__ uint32_t fill_off(int u) {
    const int r = u >> 4, cu = u & 15;
    return (uint32_t)(r * 256 + ((cu >> 3) << 7) + (((cu & 7) * 16) ^ ((r & 7) << 4)));
}

// Compute one BK=128 tile (8 x k16); optionally interleave next-stage fill.
// 256 threads: 8 A-chunks + 6 B-chunks per thread, spread over ks 0..4.
template <bool PH, bool FILL>
__device__ __forceinline__ void compute_tile(
    uint32_t stg, uint32_t fstg, uint32_t aoff0, uint32_t boff0,
    uint32_t fA0, uint32_t fB0,
    const __half*& pA0, const __half* (&pB)[6],
    float (&alo)[2][6][4], float (&ahi)[2][2][4])
{
    uint32_t a[2][2][4];   // A double buffer [buf][mi][reg]
    uint32_t b[6][2];      // B single buffer

    #pragma unroll
    for (int mi = 0; mi < 2; mi++)
        ldsm4(a[0][mi][0], a[0][mi][1], a[0][mi][2], a[0][mi][3],
              stg + aoff0 + mi * 4096);
    #pragma unroll
    for (int p = 0; p < 3; p++)
        ldsm4(b[2 * p][0], b[2 * p][1], b[2 * p + 1][0], b[2 * p + 1][1],
              stg + boff0 + p * 4096);

    #pragma unroll
    for (int ks = 0; ks < 8; ks++) {
        const int cur = ks & 1, nxt = cur ^ 1;
        if (ks < 7) {
            const uint32_t kx = (uint32_t)((ks + 1) << 5);
            #pragma unroll
            for (int mi = 0; mi < 2; mi++)
                ldsm4(a[nxt][mi][0], a[nxt][mi][1], a[nxt][mi][2], a[nxt][mi][3],
                      stg + (aoff0 ^ kx) + mi * 4096);
        }
        if (FILL) {
            if (ks < 2) {              // A: 4 chunks per ks
                #pragma unroll
                for (int i = 0; i < 4; i++) {
                    const int j = 4 * ks + i;
                    cp16(fstg + fA0 + (uint32_t)j * 4096u, pA0 + j * 8192);
                }
            } else if (ks < 5) {       // B: 2 chunks per ks
                const int i0 = 2 * (ks - 2);
                cp16(fstg + fB0 + (uint32_t)i0 * 4096u, pB[i0]);
                cp16(fstg + fB0 + (uint32_t)(i0 + 1) * 4096u, pB[i0 + 1]);
                if (ks == 4) CP_COMMIT();
            }
        }
        #pragma unroll
        for (int mi = 0; mi < 2; mi++) {
            #pragma unroll
            for (int nb = 0; nb < 6; nb++) {
                if (PH && nb >= 4)
                    mma16(ahi[mi][nb - 4], a[cur][mi], b[nb][0], b[nb][1]);
                else
                    mma16(alo[mi][nb], a[cur][mi], b[nb][0], b[nb][1]);
            }
        }
        if (ks < 7) {
            const uint32_t kx = (uint32_t)((ks + 1) << 5);
            #pragma unroll
            for (int p = 0; p < 3; p++)
                ldsm4(b[2 * p][0], b[2 * p][1], b[2 * p + 1][0], b[2 * p + 1][1],
                      stg + (boff0 ^ kx) + p * 4096);
        }
    }
    if (FILL) {
        pA0 += 128;
        #pragma unroll
        for (int i = 0; i < 6; i++) pB[i] += 128;
    }
}

__global__ void __launch_bounds__(256, 2)
gru_mma_kernel(const float* __restrict__ hidden,
               const float* __restrict__ bg, const float* __restrict__ bi,
               const float* __restrict__ bh, float* __restrict__ out)
{
    extern __shared__ char dsm[];
    const int tid  = threadIdx.x;
    const int lane = tid & 31;
    const int wid  = tid >> 5;
    const int wm   = wid >> 1;          // 0..3 (M, 32 rows each)
    const int wn   = wid & 1;           // 0..1 (N slice, 16 units each)
    const int n0 = blockIdx.x * 32;     // hidden-unit slice
    const int m0 = blockIdx.y * 128;    // batch-row slice

    const __half* cIn  = g_cvt + OFF_IN;
    const __half* cHid = g_cvt + OFF_HID;
    const __half* cWg  = g_cvt + OFF_WG;
    const __half* cWi  = g_cvt + OFF_WI;
    const __half* cWh  = g_cvt + OFF_WH;

    const uint32_t raw = smem_u32(dsm);
    const uint32_t sb  = (raw + 127u) & ~127u;  // 128B align suffices (swizzle
                                                // is relative within 256B rows)
    const uint32_t stage0 = sb;
    const uint32_t stage1 = stage0 + STAGE_BYTES;

    // ---- fill state (16B chunk = 8 halfs; 16 chunks per 256B row) ----
    const uint32_t fA0 = fill_off(tid);                        // + j*4096
    const uint32_t fB0 = (uint32_t)A_BYTES + fill_off(tid);    // + i*4096
    const int frow = tid >> 4, fcu = (tid & 15) * 8;
    const __half* pA0 = cIn + (m0 + frow) * 512 + fcu;         // + j*8192 halfs
    const __half* pB[6];
    bool isw[6];
    #pragma unroll
    for (int i = 0; i < 6; i++) {
        const int r = frow + 16 * i;        // 0..95
        const int ws = (r >= 48) ? 1 : 0, rr = r - ws * 48;
        const int un = n0 + ws * 16;
        isw[i] = (rr >= 32);
        if (rr < 16)       pB[i] = cWg + (un + rr) * 1024 + fcu;
        else if (rr < 32)  pB[i] = cWg + (512 + un + rr - 16) * 1024 + fcu;
        else               pB[i] = cWi + (un + rr - 32) * 512 + fcu;
    }
    // Phase switch (after 4 fills of +128): xa = in+row*512+512 -> hid+row*512.
    const ptrdiff_t dxa = (cHid - cIn) - 512;
    const ptrdiff_t dwh = (cWh - cWi) - 512;

    // ---- LDSM base offsets ----
    uint32_t aoff0, boff0;
    {
        const uint32_t arow = (uint32_t)(wm * 32 + (lane & 7) + ((lane >> 3) & 1) * 8);
        const uint32_t acb  = (uint32_t)((lane >> 4) * 16);
        const uint32_t brow = (uint32_t)(wn * 48 + ((lane >> 4) * 8) + (lane & 7));
        const uint32_t bcb  = (uint32_t)(((lane >> 3) & 1) * 16);
        aoff0 = arow * 256 + (acb ^ ((arow & 7) << 4));                     // + mi*4096
        boff0 = (uint32_t)A_BYTES + brow * 256 + (bcb ^ ((brow & 7) << 4)); // + p*4096
    }

    float alo[2][6][4];
    float ahi[2][2][4];
    #pragma unroll
    for (int mi = 0; mi < 2; mi++) {
        #pragma unroll
        for (int nb = 0; nb < 6; nb++)
            #pragma unroll
            for (int e = 0; e < 4; e++) alo[mi][nb][e] = 0.0f;
        #pragma unroll
        for (int nb = 0; nb < 2; nb++)
            #pragma unroll
            for (int e = 0; e < 4; e++) ahi[mi][nb][e] = 0.0f;
    }

    // prologue: fill stage0 for kt=0
    {
        #pragma unroll
        for (int j = 0; j < 8; j++)
            cp16(stage0 + fA0 + (uint32_t)j * 4096u, pA0 + j * 8192);
        pA0 += 128;
        #pragma unroll
        for (int i = 0; i < 6; i++) {
            cp16(stage0 + fB0 + (uint32_t)i * 4096u, pB[i]);
            pB[i] += 128;
        }
        CP_COMMIT();
    }

    // Phase 0: kt = 0..3 (X=input, ih=Wi -> alo)
    #pragma unroll 2
    for (int kt = 0; kt < 4; kt++) {
        const uint32_t stg  = (kt & 1) ? stage1 : stage0;
        const uint32_t fstg = (kt & 1) ? stage0 : stage1;
        CP_WAIT0();
        __syncthreads();
        if (kt == 3) {   // next fill f=4: switch xa->hidden, Wi->Wh
            pA0 += dxa;
            #pragma unroll
            for (int i = 0; i < 6; i++) if (isw[i]) pB[i] += dwh;
        }
        compute_tile<false, true>(stg, fstg, aoff0, boff0, fA0, fB0,
                                  pA0, pB, alo, ahi);
    }
    // Phase 1: kt = 4..7 (X=hidden, ih=Wh -> ahi); last iter fills nothing.
    #pragma unroll 2
    for (int kt = 4; kt < 7; kt++) {
        const uint32_t stg  = (kt & 1) ? stage1 : stage0;
        const uint32_t fstg = (kt & 1) ? stage0 : stage1;
        CP_WAIT0();
        __syncthreads();
        compute_tile<true, true>(stg, fstg, aoff0, boff0, fA0, fB0,
                                 pA0, pB, alo, ahi);
    }
    {
        CP_WAIT0();
        __syncthreads();
        compute_tile<true, false>(stage1, stage0, aoff0, boff0, fA0, fB0,
                                  pA0, pB, alo, ahi);
    }

    // ---- register-resident epilogue (biases from global, fp32 hidden) ----
    #pragma unroll
    for (int mi = 0; mi < 2; mi++) {
        #pragma unroll
        for (int unb = 0; unb < 2; unb++) {
            const int ug = n0 + wn * 16 + unb * 8 + 2 * (lane & 3);  // global unit
            const float br0 = __ldg(&bg[ug]),        br1 = __ldg(&bg[ug + 1]);
            const float bz0 = __ldg(&bg[512 + ug]),  bz1 = __ldg(&bg[512 + ug + 1]);
            const float bi0 = __ldg(&bi[ug]),        bi1 = __ldg(&bi[ug + 1]);
            const float bh0 = __ldg(&bh[ug]),        bh1 = __ldg(&bh[ug + 1]);
            #pragma unroll
            for (int half = 0; half < 2; half++) {
                const int m = wm * 32 + mi * 16 + (lane >> 2) + 8 * half;
                const float rv0 = fsigmoid(alo[mi][0 + unb][2 * half]     + br0);
                const float rv1 = fsigmoid(alo[mi][0 + unb][2 * half + 1] + br1);
                const float zv0 = fsigmoid(alo[mi][2 + unb][2 * half]     + bz0);
                const float zv1 = fsigmoid(alo[mi][2 + unb][2 * half + 1] + bz1);
                const float iv0 = alo[mi][4 + unb][2 * half];
                const float iv1 = alo[mi][4 + unb][2 * half + 1];
                const float hv0 = ahi[mi][unb][2 * half];
                const float hv1 = ahi[mi][unb][2 * half + 1];
                const float2 hg = *(const float2*)&hidden[(m0 + m) * 512 + ug];
                const float ng0 = ftanh(iv0 + bi0 + rv0 * (hv0 + bh0));
                const float ng1 = ftanh(iv1 + bi1 + rv1 * (hv1 + bh1));
                float2 o;
                o.x = (1.0f - zv0) * ng0 + zv0 * hg.x;
                o.y = (1.0f - zv1) * ng1 + zv1 * hg.y;
                *(float2*)&out[(m0 + m) * 512 + ug] = o;
            }
        }
    }
}

extern "C" void kernel_launch(void* const* d_in, const int* in_sizes, int n_in,
                              void* d_out, int out_size)
{
    const float* input  = (const float*)d_in[0];
    const float* hidden = (const float*)d_in[1];
    const float* Wg     = (const float*)d_in[2];
    const float* bg     = (const float*)d_in[3];
    const float* Wi     = (const float*)d_in[4];
    const float* bi     = (const float*)d_in[5];
    const float* Wh     = (const float*)d_in[6];
    const float* bh     = (const float*)d_in[7];
    float* out = (float*)d_out;

    // fp32 -> fp16 conversion pre-pass
    cvt_kernel<<<(2097152 + 255) / 256, 256>>>((const float4*)input,  OFF_IN,  2097152);
    cvt_kernel<<<(2097152 + 255) / 256, 256>>>((const float4*)hidden, OFF_HID, 2097152);
    cvt_kernel<<<(262144  + 255) / 256, 256>>>((const float4*)Wg,     OFF_WG,  262144);
    cvt_kernel<<<(65536   + 255) / 256, 256>>>((const float4*)Wi,     OFF_WI,  65536);
    cvt_kernel<<<(65536   + 255) / 256, 256>>>((const float4*)Wh,     OFF_WH,  65536);

    cudaFuncSetAttribute(gru_mma_kernel,
                         cudaFuncAttributeMaxDynamicSharedMemorySize, SMEM_BYTES);
    // grid.x = 16 n-slices of 32 units, grid.y = 128 batch tiles of 128 rows
    gru_mma_kernel<<<dim3(16, 128), 256, SMEM_BYTES>>>(hidden, bg, bi, bh, out);
}